// round 12
// baseline (speedup 1.0000x reference)
#include <cuda_runtime.h>
#include <cuda_bf16.h>
#include <math.h>

#define NNODE 10000
#define FDIM  128
#define NB    2
#define NT    8
#define EMAX  321000
#define BATCH (NNODE * FDIM)

// ---------------- device scratch ----------------
__device__ int   g_e64;
__device__ float g_deg[NNODE];
__device__ float g_dinv[NNODE];
__device__ int   g_counts[NNODE];
__device__ int   g_colptr[NNODE + 1];
__device__ int   g_cursor[NNODE];
__device__ int2  g_csr[EMAX];                 // {src, val bits}
__device__ float g_pnorm[2];
__device__ float g_scores0[NT * NB * NNODE];
__device__ float g_scores1All[NT * NB * NNODE];
__device__ __align__(16) float g_pooled0[NT * NB * 16384];
__device__ __align__(16) float g_pooled1All[NT * NB * 16384];
__device__ __align__(16) float g_H0A[NB * 16384];
__device__ __align__(16) float g_H0B[NB * 16384];
__device__ __align__(16) float g_H1A[NB * 16384];
__device__ __align__(16) float g_H1B[NB * 16384];
__device__ __align__(16) float g_HT0All[NT * NB * 16384];  // [t][b][k][j]
__device__ __align__(16) float g_HT1[NB * 16384];
__device__ __align__(16) float g_tmpAll[NT * NB * BATCH];  // 82 MB
__device__ __align__(16) float g_out0All[NT * NB * BATCH]; // 82 MB

__device__ __forceinline__ void read_edge(const void* ei, int e, int E, int& s, int& t) {
    if (g_e64) {
        const long long* p = (const long long*)ei;
        s = (int)p[e]; t = (int)p[E + e];
    } else {
        const int* p = (const int*)ei;
        s = p[e]; t = p[E + e];
    }
}

__device__ __forceinline__ unsigned int fkey(float f) {
    unsigned int b = __float_as_uint(f);
    return (b & 0x80000000u) ? ~b : (b | 0x80000000u);
}

__device__ __forceinline__ unsigned long long pk2(float v) {
    unsigned long long r;
    asm("mov.b64 %0, {%1, %1};" : "=l"(r) : "f"(v));
    return r;
}
__device__ __forceinline__ float2 up2(unsigned long long v) {
    float2 r;
    asm("mov.b64 {%0, %1}, %2;" : "=f"(r.x), "=f"(r.y) : "l"(v));
    return r;
}
#define FFMA2(acc, a, b) asm("fma.rn.f32x2 %0, %1, %2, %0;" : "+l"(acc) : "l"(a), "l"(b))

// ---------------- preprocessing ----------------
__global__ void init_kernel(const int* ei32, int E,
                            const float* __restrict__ p,
                            const float* __restrict__ W0) {
    int gid = blockIdx.x * 256 + threadIdx.x;
    if (gid < NNODE) { g_deg[gid] = 0.f; g_counts[gid] = 0; }
    if (gid < 65536) {
        int c = gid >> 15;
        int b = (gid >> 14) & 1;
        int ji = gid & 16383;
        int j = ji >> 7, i2 = ji & 127;
        float v = W0[c * 16384 + i2 * 128 + j];   // H[c][b][j][i] = W0[c][i][j]
        float* H = (c == 0) ? g_H0A : g_H1A;
        H[b * 16384 + ji] = v;
    }
    if (blockIdx.x == 255) {
        __shared__ int any;
        if (threadIdx.x == 0) any = 0;
        __syncthreads();
        int lim = min(2048, E / 2);
        for (int i = threadIdx.x; i < lim; i += 256)
            if (ei32[2 * i + 1] != 0) any = 1;
        __syncthreads();
        if (threadIdx.x == 0) g_e64 = (any == 0) ? 1 : 0;
    }
    if (blockIdx.x == 254 && threadIdx.x < 64) {
        int w = threadIdx.x >> 5, l = threadIdx.x & 31;
        const float* pc = p + w * 128;
        float s = 0.f;
        for (int i = l; i < 128; i += 32) { float v = pc[i]; s += v * v; }
        #pragma unroll
        for (int o = 16; o > 0; o >>= 1) s += __shfl_down_sync(0xffffffffu, s, o);
        if (l == 0) g_pnorm[w] = sqrtf(s);
    }
}

__global__ void deg_kernel(const void* ei, const float* __restrict__ ew, int E) {
    int e = blockIdx.x * 256 + threadIdx.x;
    if (e >= E) return;
    int s, t;
    read_edge(ei, e, E, s, t);
    atomicAdd(&g_deg[t], ew[e]);
    atomicAdd(&g_counts[t], 1);
}

__global__ void scan_kernel() {
    __shared__ int part[256];
    int tid = threadIdx.x;
    int start = tid * 40;
    int s = 0;
    for (int j = 0; j < 40; ++j) {
        int idx = start + j;
        if (idx < NNODE) s += g_counts[idx];
    }
    part[tid] = s;
    __syncthreads();
    for (int off = 1; off < 256; off <<= 1) {
        int v = (tid >= off) ? part[tid - off] : 0;
        __syncthreads();
        part[tid] += v;
        __syncthreads();
    }
    int run = part[tid] - s;
    for (int j = 0; j < 40; ++j) {
        int idx = start + j;
        if (idx < NNODE) {
            g_colptr[idx] = run; g_cursor[idx] = run;
            run += g_counts[idx];
            g_dinv[idx] = rsqrtf(g_deg[idx] + 1.0f);
        }
    }
    if (tid == 255) g_colptr[NNODE] = part[255];
}

__global__ void fill_kernel(const void* ei, const float* __restrict__ ew, int E) {
    int e = blockIdx.x * 256 + threadIdx.x;
    if (e >= E) return;
    int s, t;
    read_edge(ei, e, E, s, t);
    int pos = atomicAdd(&g_cursor[t], 1);
    g_csr[pos] = make_int2(s, __float_as_int(g_dinv[s] * ew[e]));
}

__global__ void scores0_kernel(const float* __restrict__ x, const float* __restrict__ p0) {
    int wid = (blockIdx.x << 3) + (threadIdx.x >> 5);
    if (wid >= NT * NB * NNODE) return;
    int lane = threadIdx.x & 31;
    int t = wid / (NB * NNODE);
    int rem = wid - t * (NB * NNODE);
    int b = rem / NNODE;
    int n = rem - b * NNODE;
    const float* xr = x + (((size_t)(b * NT + t)) * NNODE + n) * FDIM;
    float4 v = __ldg((const float4*)xr + lane);
    float4 pv = __ldg((const float4*)p0 + lane);
    float s = v.x * pv.x + v.y * pv.y + v.z * pv.z + v.w * pv.w;
    #pragma unroll
    for (int o = 16; o > 0; o >>= 1) s += __shfl_down_sync(0xffffffffu, s, o);
    if (lane == 0) g_scores0[wid] = s / g_pnorm[0];
}

// ================= roles (256-thread) =================

// ---- top-k 128 of 10000 + pool; 256 threads; tb = t*2+b ----
#define TKCAP 1024
#define TOPK_SMEM 21760
__device__ void topk_role(int tb, int mode, const float* __restrict__ x, char* smraw) {
    int* histW = (int*)smraw;                           // [8][256] 8192B
    unsigned int* cKey = (unsigned int*)(smraw + 8192); // 4096B
    int* cIdx = (int*)(smraw + 12288);                  // 4096B
    float* cVal = (float*)(smraw + 16384);              // 4096B
    int* rIdx = (int*)(smraw + 20480);                  // 512B
    float* rTanh = (float*)(smraw + 20992);             // 512B
    int* scl = (int*)(smraw + 21504);                   // sCnt,sSel,sAdd

    int tid = threadIdx.x;
    int grp = tid >> 5;   // 8 warps -> 8 private histograms

    const float* sc;
    const float* feat;
    float* pool;
    if (mode == 0) {
        int t = tb >> 1, b = tb & 1;
        sc = g_scores0 + (size_t)tb * NNODE;
        feat = x + ((size_t)(b * NT + t)) * BATCH;
        pool = g_pooled0 + (size_t)tb * 16384;
    } else {
        sc = g_scores1All + (size_t)tb * NNODE;
        feat = g_out0All + (size_t)tb * BATCH;
        pool = g_pooled1All + (size_t)tb * 16384;
    }

    unsigned int prefix = 0, pmask = 0;
    int K = 128;
    for (int shift = 24; shift >= 0; shift -= 8) {
        for (int i = tid; i < 8 * 256; i += 256) histW[i] = 0;
        __syncthreads();
        for (int n = tid; n < NNODE; n += 256) {
            unsigned int kk = fkey(sc[n]);
            if ((kk & pmask) == prefix) atomicAdd(&histW[grp * 256 + ((kk >> shift) & 255)], 1);
        }
        __syncthreads();
        if (tid < 256) {
            int s = 0;
            #pragma unroll
            for (int g = 0; g < 8; ++g) s += histW[g * 256 + tid];
            __syncthreads();
            histW[tid] = s;
        }
        __syncthreads();
        if (tid == 0) {
            int cum = 0, bsel = 0;
            for (int bkt = 255; bkt >= 0; --bkt) {
                int h = histW[bkt];
                if (cum + h >= K) { bsel = bkt; break; }
                cum += h;
            }
            scl[1] = bsel; scl[2] = cum;
        }
        __syncthreads();
        prefix |= ((unsigned int)scl[1]) << shift;
        pmask |= 0xFFu << shift;
        K -= scl[2];
        __syncthreads();
    }
    if (tid == 0) scl[0] = 0;
    __syncthreads();
    for (int n = tid; n < NNODE; n += 256) {
        float v = sc[n];
        unsigned int kk = fkey(v);
        if (kk >= prefix) {
            int pos = atomicAdd(&scl[0], 1);
            if (pos < TKCAP) { cKey[pos] = kk; cIdx[pos] = n; cVal[pos] = v; }
        }
    }
    __syncthreads();
    int C = min(scl[0], TKCAP);
    for (int i = tid; i < C; i += 256) {
        unsigned int ki = cKey[i];
        int ii = cIdx[i];
        int rank = 0;
        for (int j = 0; j < C; ++j) {
            unsigned int kj = cKey[j];
            rank += (kj > ki) || (kj == ki && cIdx[j] < ii);
        }
        if (rank < 128) { rIdx[rank] = ii; rTanh[rank] = tanhf(cVal[i]); }
    }
    __syncthreads();
    for (int i = tid; i < 4096; i += 256) {
        int row = i >> 5, q = i & 31;
        float4 v = __ldg((const float4*)(feat + (size_t)rIdx[row] * FDIM) + q);
        float s = rTanh[row];
        v.x *= s; v.y *= s; v.z *= s; v.w *= s;
        *((float4*)(pool + row * 128) + q) = v;
    }
}

// ---- GRU step; 256 threads; rb in [0,128) ----
__device__ void gru_role(int rb,
                         const float* __restrict__ xg, const float* __restrict__ Hin,
                         float* __restrict__ Hout, float* __restrict__ HTdst,
                         const float* __restrict__ w_ih, const float* __restrict__ w_hh,
                         const float* __restrict__ b_ih, const float* __restrict__ b_hh,
                         float* sm) {
    float* xs = sm;               // [16][33]
    float* hs = sm + 528;         // [16][33]
    float* wi = sm + 1056;        // [3][16][33]
    float* wh = sm + 2640;        // [3][16][33]
    int tid = threadIdx.x;
    int r0 = (rb & 15) * 16;
    int h0 = (rb >> 4) * 16;
    int hh = tid & 15, rr = tid >> 4;
    float acc[6] = {0.f, 0.f, 0.f, 0.f, 0.f, 0.f};

    for (int kc = 0; kc < 128; kc += 32) {
        for (int i = tid; i < 512; i += 256) {
            int r = i >> 5, k = i & 31;
            xs[r * 33 + k] = xg[(r0 + r) * 128 + kc + k];
            hs[r * 33 + k] = Hin[(r0 + r) * 128 + kc + k];
        }
        #pragma unroll
        for (int g = 0; g < 3; ++g)
            for (int i = tid; i < 512; i += 256) {
                int r = i >> 5, k = i & 31;
                wi[g * 528 + r * 33 + k] = w_ih[(g * 128 + h0 + r) * 128 + kc + k];
                wh[g * 528 + r * 33 + k] = w_hh[(g * 128 + h0 + r) * 128 + kc + k];
            }
        __syncthreads();
        #pragma unroll
        for (int k = 0; k < 32; ++k) {
            float xv = xs[rr * 33 + k], hv = hs[rr * 33 + k];
            acc[0] = fmaf(xv, wi[0 * 528 + hh * 33 + k], acc[0]);
            acc[1] = fmaf(xv, wi[1 * 528 + hh * 33 + k], acc[1]);
            acc[2] = fmaf(xv, wi[2 * 528 + hh * 33 + k], acc[2]);
            acc[3] = fmaf(hv, wh[0 * 528 + hh * 33 + k], acc[3]);
            acc[4] = fmaf(hv, wh[1 * 528 + hh * 33 + k], acc[4]);
            acc[5] = fmaf(hv, wh[2 * 528 + hh * 33 + k], acc[5]);
        }
        __syncthreads();
    }
    int row = r0 + rr, h = h0 + hh;
    float gir = acc[0] + b_ih[h], giz = acc[1] + b_ih[128 + h], gin = acc[2] + b_ih[256 + h];
    float ghr = acc[3] + b_hh[h], ghz = acc[4] + b_hh[128 + h], ghn = acc[5] + b_hh[256 + h];
    float r = 1.f / (1.f + expf(-(gir + ghr)));
    float z = 1.f / (1.f + expf(-(giz + ghz)));
    float n = tanhf(fmaf(r, ghn, gin));
    float hv = (1.f - z) * n + z * Hin[row * 128 + h];
    Hout[row * 128 + h] = hv;
    int b = row >> 7, j = row & 127;
    HTdst[(size_t)b * 16384 + h * 128 + j] = hv;
}

// ---- GEMM (split-K, 49KB smem): C[idx,n,j] = sum_k A[n,k]*HT[idx,k,j]; rb in [0,314) ----
__device__ void gemm_role(int rb, const float* __restrict__ A, long sy,
                          const float* __restrict__ HT, float* __restrict__ C, float* sm) {
    float* As = sm;               // [64][64]
    float* Hs = sm + 64 * 64;     // [64][132]
    int idx = rb / 157;
    int rowBase = (rb % 157) * 64;
    const float* Ab = A + (size_t)idx * sy;
    const float* HTb = HT + (size_t)idx * 16384;
    float* Cb = C + (size_t)idx * BATCH;
    int tid = threadIdx.x;
    int c0 = (tid & 15) * 4;
    int r0 = (tid >> 4) * 4;

    unsigned long long aA[4][2], aB[4][2];
    #pragma unroll
    for (int i = 0; i < 4; ++i) { aA[i][0] = aA[i][1] = aB[i][0] = aB[i][1] = 0ull; }

    #pragma unroll
    for (int kh = 0; kh < 2; ++kh) {
        if (kh) __syncthreads();
        for (int i = tid; i < 64 * 128; i += 256) {
            int k = i >> 7, j = i & 127;
            Hs[k * 132 + j] = HTb[(kh * 64 + k) * 128 + j];
        }
        for (int i = tid; i < 64 * 16; i += 256) {
            int r = i >> 4, c4 = i & 15;
            int row = rowBase + r;
            float4 v = (row < NNODE)
                ? __ldg((const float4*)(Ab + (size_t)row * 128 + kh * 64) + c4)
                : make_float4(0.f, 0.f, 0.f, 0.f);
            *((float4*)(As + r * 64) + c4) = v;
        }
        __syncthreads();
        const float* ar = As + r0 * 64;
        #pragma unroll 4
        for (int k = 0; k < 64; ++k) {
            ulonglong2 hA = *(const ulonglong2*)(Hs + k * 132 + c0);
            ulonglong2 hB = *(const ulonglong2*)(Hs + k * 132 + c0 + 64);
            #pragma unroll
            for (int i = 0; i < 4; ++i) {
                unsigned long long ap = pk2(ar[i * 64 + k]);
                FFMA2(aA[i][0], ap, hA.x);
                FFMA2(aA[i][1], ap, hA.y);
                FFMA2(aB[i][0], ap, hB.x);
                FFMA2(aB[i][1], ap, hB.y);
            }
        }
    }
    #pragma unroll
    for (int i = 0; i < 4; ++i) {
        int row = rowBase + r0 + i;
        if (row < NNODE) {
            float2 l0 = up2(aA[i][0]), l1 = up2(aA[i][1]);
            float2 m0 = up2(aB[i][0]), m1 = up2(aB[i][1]);
            *((float4*)(Cb + (size_t)row * 128 + c0)) = make_float4(l0.x, l0.y, l1.x, l1.y);
            *((float4*)(Cb + (size_t)row * 128 + c0 + 64)) = make_float4(m0.x, m0.y, m1.x, m1.y);
        }
    }
}

// ---- propagation: 4 nodes per 256-thread block (independent 64-thr subgroups) ----
__device__ void prop_role(int rb, const float* __restrict__ tmp2, float* __restrict__ out2,
                          float* __restrict__ sc2, const float* __restrict__ p1,
                          const float* __restrict__ biasc) {
    int tid = threadIdx.x;
    int sub = tid >> 6;
    int b = (tid >> 5) & 1;
    int q = tid & 31;
    int i = rb * 4 + sub;
    const float* tb = tmp2 + (size_t)b * BATCH;
    int e0 = g_colptr[i], e1 = g_colptr[i + 1];
    float4 acc = make_float4(0.f, 0.f, 0.f, 0.f);

    int e = e0;
    for (; e + 4 <= e1; e += 4) {
        int2 c0v = __ldg(&g_csr[e]);
        int2 c1v = __ldg(&g_csr[e + 1]);
        int2 c2v = __ldg(&g_csr[e + 2]);
        int2 c3v = __ldg(&g_csr[e + 3]);
        float4 r0 = __ldg((const float4*)(tb + (size_t)c0v.x * 128) + q);
        float4 r1 = __ldg((const float4*)(tb + (size_t)c1v.x * 128) + q);
        float4 r2 = __ldg((const float4*)(tb + (size_t)c2v.x * 128) + q);
        float4 r3 = __ldg((const float4*)(tb + (size_t)c3v.x * 128) + q);
        float v0 = __int_as_float(c0v.y), v1 = __int_as_float(c1v.y);
        float v2 = __int_as_float(c2v.y), v3 = __int_as_float(c3v.y);
        acc.x = fmaf(v0, r0.x, acc.x); acc.y = fmaf(v0, r0.y, acc.y);
        acc.z = fmaf(v0, r0.z, acc.z); acc.w = fmaf(v0, r0.w, acc.w);
        acc.x = fmaf(v1, r1.x, acc.x); acc.y = fmaf(v1, r1.y, acc.y);
        acc.z = fmaf(v1, r1.z, acc.z); acc.w = fmaf(v1, r1.w, acc.w);
        acc.x = fmaf(v2, r2.x, acc.x); acc.y = fmaf(v2, r2.y, acc.y);
        acc.z = fmaf(v2, r2.z, acc.z); acc.w = fmaf(v2, r2.w, acc.w);
        acc.x = fmaf(v3, r3.x, acc.x); acc.y = fmaf(v3, r3.y, acc.y);
        acc.z = fmaf(v3, r3.z, acc.z); acc.w = fmaf(v3, r3.w, acc.w);
    }
    for (; e < e1; ++e) {
        int2 sv = __ldg(&g_csr[e]);
        float v = __int_as_float(sv.y);
        float4 r = __ldg((const float4*)(tb + (size_t)sv.x * 128) + q);
        acc.x = fmaf(v, r.x, acc.x); acc.y = fmaf(v, r.y, acc.y);
        acc.z = fmaf(v, r.z, acc.z); acc.w = fmaf(v, r.w, acc.w);
    }
    float di = g_dinv[i];
    size_t soff = (size_t)i * 128;
    float4 sv = __ldg((const float4*)(tb + soff) + q);
    acc.x = fmaf(di, sv.x, acc.x); acc.y = fmaf(di, sv.y, acc.y);
    acc.z = fmaf(di, sv.z, acc.z); acc.w = fmaf(di, sv.w, acc.w);
    float4 bb = __ldg((const float4*)biasc + q);
    float4 o;
    o.x = fmaxf(fmaf(di, acc.x, bb.x), 0.f);
    o.y = fmaxf(fmaf(di, acc.y, bb.y), 0.f);
    o.z = fmaxf(fmaf(di, acc.z, bb.z), 0.f);
    o.w = fmaxf(fmaf(di, acc.w, bb.w), 0.f);
    __stcs((float4*)(out2 + (size_t)b * BATCH + soff) + q, o);
    float4 pv = __ldg((const float4*)p1 + q);
    float s = o.x * pv.x + o.y * pv.y + o.z * pv.z + o.w * pv.w;
    #pragma unroll
    for (int off = 16; off > 0; off >>= 1) s += __shfl_down_sync(0xffffffffu, s, off);
    if (q == 0) sc2[b * NNODE + i] = s / g_pnorm[1];
}

// ================= mega kernel: role dispatch =================
#define PIPE_SMEM 50176
__global__ void __launch_bounds__(256, 4) pipe_kernel(
        int nProp, const float* pTmp2, float* pOut2, float* pSc2,
        const float* p1, const float* bias0,
        int nGemm, const float* gA, long gSy, const float* gHT, float* gC,
        int nTopk, int topkTbBase, const float* x,
        int nGruA, const float* aXg, const float* aHin, float* aHout, float* aHT,
        const float* aWih, const float* aWhh, const float* aBih, const float* aBhh,
        int nGruB, const float* bXg, const float* bHin, float* bHout, float* bHT,
        const float* bWih, const float* bWhh, const float* bBih, const float* bBhh) {
    extern __shared__ char sm[];
    int rb = blockIdx.x;
    if (rb < nProp) { prop_role(rb, pTmp2, pOut2, pSc2, p1, bias0); return; }
    rb -= nProp;
    if (rb < nGemm) { gemm_role(rb, gA, gSy, gHT, gC, (float*)sm); return; }
    rb -= nGemm;
    if (rb < nTopk) { topk_role(topkTbBase + rb, 1, x, sm); return; }
    rb -= nTopk;
    if (rb < nGruA) { gru_role(rb, aXg, aHin, aHout, aHT, aWih, aWhh, aBih, aBhh, (float*)sm); return; }
    rb -= nGruA;
    if (rb < nGruB) { gru_role(rb, bXg, bHin, bHout, bHT, bWih, bWhh, bBih, bBhh, (float*)sm); }
}

// standalone layer-0 topk (pre-phase)
__global__ void __launch_bounds__(256) topk0_kernel(const float* __restrict__ x) {
    extern __shared__ char sm[];
    topk_role(blockIdx.x, 0, x, sm);
}

// ---------------- final propagation (2 tb) ----------------
__global__ void __launch_bounds__(64) prop_final_kernel(const float* __restrict__ tmpAll,
                                                        float* __restrict__ dout,
                                                        const float* __restrict__ biasc) {
    __shared__ int2 se[64];
    int i = blockIdx.x;
    int tid = threadIdx.x;
    int b = tid >> 5, q = tid & 31;
    const float* tb = tmpAll + (size_t)b * BATCH;
    int e0 = g_colptr[i], e1 = g_colptr[i + 1];
    float4 acc = make_float4(0.f, 0.f, 0.f, 0.f);

    for (int base = e0; base < e1; base += 64) {
        int m = min(64, e1 - base);
        __syncthreads();
        if (tid < m) se[tid] = g_csr[base + tid];
        __syncthreads();
        #pragma unroll 8
        for (int e = 0; e < m; ++e) {
            int2 sv = se[e];
            float v = __int_as_float(sv.y);
            float4 r = __ldg((const float4*)(tb + (size_t)sv.x * 128) + q);
            acc.x = fmaf(v, r.x, acc.x); acc.y = fmaf(v, r.y, acc.y);
            acc.z = fmaf(v, r.z, acc.z); acc.w = fmaf(v, r.w, acc.w);
        }
    }
    float di = g_dinv[i];
    float4 sv = __ldg((const float4*)(tb + (size_t)i * 128) + q);
    acc.x = fmaf(di, sv.x, acc.x); acc.y = fmaf(di, sv.y, acc.y);
    acc.z = fmaf(di, sv.z, acc.z); acc.w = fmaf(di, sv.w, acc.w);
    float4 bb = __ldg((const float4*)biasc + q);
    float4 o;
    o.x = fmaxf(fmaf(di, acc.x, bb.x), 0.f);
    o.y = fmaxf(fmaf(di, acc.y, bb.y), 0.f);
    o.z = fmaxf(fmaf(di, acc.z, bb.z), 0.f);
    o.w = fmaxf(fmaf(di, acc.w, bb.w), 0.f);
    *((float4*)(dout + (size_t)b * BATCH + (size_t)i * 128) + q) = o;
}

// ---------------- launcher: single-stream software pipeline ----------------
extern "C" void kernel_launch(void* const* d_in, const int* in_sizes, int n_in,
                              void* d_out, int out_size) {
    const float* x   = (const float*)d_in[0];
    const void*  ei  = d_in[1];
    const float* ew  = (const float*)d_in[2];
    const float* W0  = (const float*)d_in[3];
    const float* p   = (const float*)d_in[4];
    const float* wih = (const float*)d_in[5];
    const float* whh = (const float*)d_in[6];
    const float* bih = (const float*)d_in[7];
    const float* bhh = (const float*)d_in[8];
    const float* bias = (const float*)d_in[9];
    float* dout = (float*)d_out;
    int E = in_sizes[2];

    cudaFuncSetAttribute(pipe_kernel, cudaFuncAttributeMaxDynamicSharedMemorySize, PIPE_SMEM);

    float *pH0A, *pH0B, *pH1A, *pH1B, *pHT0, *pHT1, *pP0, *pP1, *pTmp, *pOut0, *pSc1;
    cudaGetSymbolAddress((void**)&pH0A, g_H0A);
    cudaGetSymbolAddress((void**)&pH0B, g_H0B);
    cudaGetSymbolAddress((void**)&pH1A, g_H1A);
    cudaGetSymbolAddress((void**)&pH1B, g_H1B);
    cudaGetSymbolAddress((void**)&pHT0, g_HT0All);
    cudaGetSymbolAddress((void**)&pHT1, g_HT1);
    cudaGetSymbolAddress((void**)&pP0, g_pooled0);
    cudaGetSymbolAddress((void**)&pP1, g_pooled1All);
    cudaGetSymbolAddress((void**)&pTmp, g_tmpAll);
    cudaGetSymbolAddress((void**)&pOut0, g_out0All);
    cudaGetSymbolAddress((void**)&pSc1, g_scores1All);

    // ---- pre-phase ----
    init_kernel<<<256, 256>>>((const int*)ei, E, p, W0);
    deg_kernel<<<(E + 255) / 256, 256>>>(ei, ew, E);
    scan_kernel<<<1, 256>>>();
    fill_kernel<<<(E + 255) / 256, 256>>>(ei, ew, E);
    scores0_kernel<<<(NT * NB * NNODE + 7) / 8, 256>>>(x, p);
    topk0_kernel<<<16, 256, TOPK_SMEM>>>(x);

    // ---- software pipeline: L(t) = prop(t-1) | gemm(t) | topk1(t-2) | gru0(t+1) | gru1(t-3) ----
    for (int t = -1; t <= 10; ++t) {
        int pt = t - 1, kt = t - 2, sA = t + 1, sB = t - 3;
        int nProp = (pt >= 0 && pt <= 7) ? 2500 : 0;
        int nGemm = (t >= 0 && t <= 7) ? 314 : 0;
        int nTopk = (kt >= 0 && kt <= 7) ? 2 : 0;
        int nGruA = (sA >= 1 && sA <= 7) ? 128 : 0;   // gru0 steps 1..7 (step 0 at t=-1 below)
        if (t == -1) { nGruA = 128; sA = 0; }          // gru0(0)
        int nGruB = (sB >= 0 && sB <= 7) ? 128 : 0;
        int total = nProp + nGemm + nTopk + nGruA + nGruB;
        if (total == 0) continue;
        int ptc = pt < 0 ? 0 : (pt > 7 ? 7 : pt);
        int ktc = kt < 0 ? 0 : (kt > 7 ? 7 : kt);
        int tc  = t  < 0 ? 0 : (t  > 7 ? 7 : t);
        int sAc = sA < 0 ? 0 : (sA > 7 ? 7 : sA);
        int sBc = sB < 0 ? 0 : (sB > 7 ? 7 : sB);
        pipe_kernel<<<total, 256, PIPE_SMEM>>>(
            nProp, pTmp + (size_t)ptc * NB * BATCH, pOut0 + (size_t)ptc * NB * BATCH,
            pSc1 + (size_t)ptc * NB * NNODE, p + 128, bias,
            nGemm, x + (size_t)tc * BATCH, (long)NT * BATCH,
            pHT0 + (size_t)tc * NB * 16384, pTmp + (size_t)tc * NB * BATCH,
            nTopk, ktc * 2, x,
            nGruA, pP0 + (size_t)sAc * 32768,
            (sAc & 1) ? pH0B : pH0A, (sAc & 1) ? pH0A : pH0B,
            pHT0 + (size_t)sAc * NB * 16384, wih, whh, bih, bhh,
            nGruB, pP1 + (size_t)sBc * 32768,
            (sBc & 1) ? pH1B : pH1A, (sBc & 1) ? pH1A : pH1B,
            pHT1, wih + 49152, whh + 49152, bih + 384, bhh + 384);
    }

    // ---- final layer-1 GEMM (t=7) + propagation to output ----
    pipe_kernel<<<314, 256, PIPE_SMEM>>>(
        0, pTmp, pOut0, pSc1, p + 128, bias,
        314, pOut0 + (size_t)14 * BATCH, (long)BATCH, pHT1, pTmp,
        0, 0, x,
        0, pP0, pH0A, pH0B, pHT0, wih, whh, bih, bhh,
        0, pP1, pH1A, pH1B, pHT1, wih + 49152, whh + 49152, bih + 384, bhh + 384);
    prop_final_kernel<<<NNODE, 64>>>(pTmp, dout, bias + 128);
}

// round 15
// speedup vs baseline: 1.2456x; 1.2456x over previous
#include <cuda_runtime.h>
#include <cuda_bf16.h>
#include <math.h>

#define NNODE 10000
#define FDIM  128
#define NB    2
#define NT    8
#define EMAX  321000
#define BATCH (NNODE * FDIM)

// ---------------- device scratch ----------------
__device__ int   g_e64;
__device__ float g_deg[NNODE];
__device__ float g_dinv[NNODE];
__device__ int   g_counts[NNODE];
__device__ int   g_colptr[NNODE + 1];
__device__ int   g_cursor[NNODE];
__device__ int2  g_csr[EMAX];                 // {src, val bits}
__device__ float g_pnorm[2];
__device__ float g_scores0[NT * NB * NNODE];
__device__ float g_scores1All[NT * NB * NNODE];
__device__ __align__(16) float g_pooled0[NT * NB * 16384];
__device__ __align__(16) float g_pooled1All[NT * NB * 16384];
__device__ __align__(16) float g_H0A[NB * 16384];
__device__ __align__(16) float g_H0B[NB * 16384];
__device__ __align__(16) float g_H1A[NB * 16384];
__device__ __align__(16) float g_H1B[NB * 16384];
__device__ __align__(16) float g_HT0All[NT * NB * 16384];  // [t][b][k][j]
__device__ __align__(16) float g_HT1[NB * 16384];
__device__ __align__(16) float g_tmpAll[NT * NB * BATCH];  // 82 MB
__device__ __align__(16) float g_out0All[NT * NB * BATCH]; // 82 MB

__device__ __forceinline__ void read_edge(const void* ei, int e, int E, int& s, int& t) {
    if (g_e64) {
        const long long* p = (const long long*)ei;
        s = (int)p[e]; t = (int)p[E + e];
    } else {
        const int* p = (const int*)ei;
        s = p[e]; t = p[E + e];
    }
}

__device__ __forceinline__ unsigned int fkey(float f) {
    unsigned int b = __float_as_uint(f);
    return (b & 0x80000000u) ? ~b : (b | 0x80000000u);
}

__device__ __forceinline__ unsigned long long pk2(float v) {
    unsigned long long r;
    asm("mov.b64 %0, {%1, %1};" : "=l"(r) : "f"(v));
    return r;
}
__device__ __forceinline__ float2 up2(unsigned long long v) {
    float2 r;
    asm("mov.b64 {%0, %1}, %2;" : "=f"(r.x), "=f"(r.y) : "l"(v));
    return r;
}
#define FFMA2(acc, a, b) asm("fma.rn.f32x2 %0, %1, %2, %0;" : "+l"(acc) : "l"(a), "l"(b))

// ---------------- preprocessing ----------------
__global__ void init_kernel(const int* ei32, int E,
                            const float* __restrict__ p,
                            const float* __restrict__ W0) {
    int gid = blockIdx.x * 256 + threadIdx.x;
    if (gid < NNODE) { g_deg[gid] = 0.f; g_counts[gid] = 0; }
    if (gid < 65536) {
        int c = gid >> 15;
        int b = (gid >> 14) & 1;
        int ji = gid & 16383;
        int j = ji >> 7, i2 = ji & 127;
        float v = W0[c * 16384 + i2 * 128 + j];   // H[c][b][j][i] = W0[c][i][j]
        float* H = (c == 0) ? g_H0A : g_H1A;
        H[b * 16384 + ji] = v;
    }
    if (blockIdx.x == 255) {
        __shared__ int any;
        if (threadIdx.x == 0) any = 0;
        __syncthreads();
        int lim = min(2048, E / 2);
        for (int i = threadIdx.x; i < lim; i += 256)
            if (ei32[2 * i + 1] != 0) any = 1;
        __syncthreads();
        if (threadIdx.x == 0) g_e64 = (any == 0) ? 1 : 0;
    }
    if (blockIdx.x == 254 && threadIdx.x < 64) {
        int w = threadIdx.x >> 5, l = threadIdx.x & 31;
        const float* pc = p + w * 128;
        float s = 0.f;
        for (int i = l; i < 128; i += 32) { float v = pc[i]; s += v * v; }
        #pragma unroll
        for (int o = 16; o > 0; o >>= 1) s += __shfl_down_sync(0xffffffffu, s, o);
        if (l == 0) g_pnorm[w] = sqrtf(s);
    }
}

__global__ void deg_kernel(const void* ei, const float* __restrict__ ew, int E) {
    int e = blockIdx.x * 256 + threadIdx.x;
    if (e >= E) return;
    int s, t;
    read_edge(ei, e, E, s, t);
    atomicAdd(&g_deg[t], ew[e]);
    atomicAdd(&g_counts[t], 1);
}

__global__ void scan_kernel() {
    __shared__ int part[256];
    int tid = threadIdx.x;
    int start = tid * 40;
    int s = 0;
    for (int j = 0; j < 40; ++j) {
        int idx = start + j;
        if (idx < NNODE) s += g_counts[idx];
    }
    part[tid] = s;
    __syncthreads();
    for (int off = 1; off < 256; off <<= 1) {
        int v = (tid >= off) ? part[tid - off] : 0;
        __syncthreads();
        part[tid] += v;
        __syncthreads();
    }
    int run = part[tid] - s;
    for (int j = 0; j < 40; ++j) {
        int idx = start + j;
        if (idx < NNODE) {
            g_colptr[idx] = run; g_cursor[idx] = run;
            run += g_counts[idx];
            g_dinv[idx] = rsqrtf(g_deg[idx] + 1.0f);
        }
    }
    if (tid == 255) g_colptr[NNODE] = part[255];
}

__global__ void fill_kernel(const void* ei, const float* __restrict__ ew, int E) {
    int e = blockIdx.x * 256 + threadIdx.x;
    if (e >= E) return;
    int s, t;
    read_edge(ei, e, E, s, t);
    int pos = atomicAdd(&g_cursor[t], 1);
    g_csr[pos] = make_int2(s, __float_as_int(g_dinv[s] * ew[e]));
}

__global__ void scores0_kernel(const float* __restrict__ x, const float* __restrict__ p0) {
    int wid = (blockIdx.x << 3) + (threadIdx.x >> 5);
    if (wid >= NT * NB * NNODE) return;
    int lane = threadIdx.x & 31;
    int t = wid / (NB * NNODE);
    int rem = wid - t * (NB * NNODE);
    int b = rem / NNODE;
    int n = rem - b * NNODE;
    const float* xr = x + (((size_t)(b * NT + t)) * NNODE + n) * FDIM;
    float4 v = __ldg((const float4*)xr + lane);
    float4 pv = __ldg((const float4*)p0 + lane);
    float s = v.x * pv.x + v.y * pv.y + v.z * pv.z + v.w * pv.w;
    #pragma unroll
    for (int o = 16; o > 0; o >>= 1) s += __shfl_down_sync(0xffffffffu, s, o);
    if (lane == 0) g_scores0[wid] = s / g_pnorm[0];
}

// ================= roles (256-thread) =================

// ---- top-k 128 of 10000 + pool; 256 threads; tb = t*2+b ----
#define TKCAP 1024
#define TOPK_SMEM 21760
__device__ void topk_role(int tb, int mode, const float* __restrict__ x, char* smraw) {
    int* histW = (int*)smraw;                           // [8][256] 8192B
    unsigned int* cKey = (unsigned int*)(smraw + 8192); // 4096B
    int* cIdx = (int*)(smraw + 12288);                  // 4096B
    float* cVal = (float*)(smraw + 16384);              // 4096B
    int* rIdx = (int*)(smraw + 20480);                  // 512B
    float* rTanh = (float*)(smraw + 20992);             // 512B
    int* scl = (int*)(smraw + 21504);                   // sCnt,sSel,sAdd

    int tid = threadIdx.x;
    int grp = tid >> 5;

    const float* sc;
    const float* feat;
    float* pool;
    if (mode == 0) {
        int t = tb >> 1, b = tb & 1;
        sc = g_scores0 + (size_t)tb * NNODE;
        feat = x + ((size_t)(b * NT + t)) * BATCH;
        pool = g_pooled0 + (size_t)tb * 16384;
    } else {
        sc = g_scores1All + (size_t)tb * NNODE;
        feat = g_out0All + (size_t)tb * BATCH;
        pool = g_pooled1All + (size_t)tb * 16384;
    }

    unsigned int prefix = 0, pmask = 0;
    int K = 128;
    for (int shift = 24; shift >= 0; shift -= 8) {
        for (int i = tid; i < 8 * 256; i += 256) histW[i] = 0;
        __syncthreads();
        for (int n = tid; n < NNODE; n += 256) {
            unsigned int kk = fkey(sc[n]);
            if ((kk & pmask) == prefix) atomicAdd(&histW[grp * 256 + ((kk >> shift) & 255)], 1);
        }
        __syncthreads();
        {
            int s = 0;
            #pragma unroll
            for (int g = 0; g < 8; ++g) s += histW[g * 256 + tid];
            __syncthreads();
            histW[tid] = s;
        }
        __syncthreads();
        if (tid == 0) {
            int cum = 0, bsel = 0;
            for (int bkt = 255; bkt >= 0; --bkt) {
                int h = histW[bkt];
                if (cum + h >= K) { bsel = bkt; break; }
                cum += h;
            }
            scl[1] = bsel; scl[2] = cum;
        }
        __syncthreads();
        prefix |= ((unsigned int)scl[1]) << shift;
        pmask |= 0xFFu << shift;
        K -= scl[2];
        __syncthreads();
    }
    if (tid == 0) scl[0] = 0;
    __syncthreads();
    for (int n = tid; n < NNODE; n += 256) {
        float v = sc[n];
        unsigned int kk = fkey(v);
        if (kk >= prefix) {
            int pos = atomicAdd(&scl[0], 1);
            if (pos < TKCAP) { cKey[pos] = kk; cIdx[pos] = n; cVal[pos] = v; }
        }
    }
    __syncthreads();
    int C = min(scl[0], TKCAP);
    for (int i = tid; i < C; i += 256) {
        unsigned int ki = cKey[i];
        int ii = cIdx[i];
        int rank = 0;
        for (int j = 0; j < C; ++j) {
            unsigned int kj = cKey[j];
            rank += (kj > ki) || (kj == ki && cIdx[j] < ii);
        }
        if (rank < 128) { rIdx[rank] = ii; rTanh[rank] = tanhf(cVal[i]); }
    }
    __syncthreads();
    for (int i = tid; i < 4096; i += 256) {
        int row = i >> 5, q = i & 31;
        float4 v = __ldg((const float4*)(feat + (size_t)rIdx[row] * FDIM) + q);
        float s = rTanh[row];
        v.x *= s; v.y *= s; v.z *= s; v.w *= s;
        *((float4*)(pool + row * 128) + q) = v;
    }
}

// ---- GRU step; 256 threads; rb in [0,128) ----
__device__ void gru_role(int rb,
                         const float* __restrict__ xg, const float* __restrict__ Hin,
                         float* __restrict__ Hout, float* __restrict__ HTdst,
                         const float* __restrict__ w_ih, const float* __restrict__ w_hh,
                         const float* __restrict__ b_ih, const float* __restrict__ b_hh,
                         float* sm) {
    float* xs = sm;               // [16][33]
    float* hs = sm + 528;
    float* wi = sm + 1056;        // [3][16][33]
    float* wh = sm + 2640;
    int tid = threadIdx.x;
    int r0 = (rb & 15) * 16;
    int h0 = (rb >> 4) * 16;
    int hh = tid & 15, rr = tid >> 4;
    float acc[6] = {0.f, 0.f, 0.f, 0.f, 0.f, 0.f};

    for (int kc = 0; kc < 128; kc += 32) {
        for (int i = tid; i < 512; i += 256) {
            int r = i >> 5, k = i & 31;
            xs[r * 33 + k] = xg[(r0 + r) * 128 + kc + k];
            hs[r * 33 + k] = Hin[(r0 + r) * 128 + kc + k];
        }
        #pragma unroll
        for (int g = 0; g < 3; ++g)
            for (int i = tid; i < 512; i += 256) {
                int r = i >> 5, k = i & 31;
                wi[g * 528 + r * 33 + k] = w_ih[(g * 128 + h0 + r) * 128 + kc + k];
                wh[g * 528 + r * 33 + k] = w_hh[(g * 128 + h0 + r) * 128 + kc + k];
            }
        __syncthreads();
        #pragma unroll
        for (int k = 0; k < 32; ++k) {
            float xv = xs[rr * 33 + k], hv = hs[rr * 33 + k];
            acc[0] = fmaf(xv, wi[0 * 528 + hh * 33 + k], acc[0]);
            acc[1] = fmaf(xv, wi[1 * 528 + hh * 33 + k], acc[1]);
            acc[2] = fmaf(xv, wi[2 * 528 + hh * 33 + k], acc[2]);
            acc[3] = fmaf(hv, wh[0 * 528 + hh * 33 + k], acc[3]);
            acc[4] = fmaf(hv, wh[1 * 528 + hh * 33 + k], acc[4]);
            acc[5] = fmaf(hv, wh[2 * 528 + hh * 33 + k], acc[5]);
        }
        __syncthreads();
    }
    int row = r0 + rr, h = h0 + hh;
    float gir = acc[0] + b_ih[h], giz = acc[1] + b_ih[128 + h], gin = acc[2] + b_ih[256 + h];
    float ghr = acc[3] + b_hh[h], ghz = acc[4] + b_hh[128 + h], ghn = acc[5] + b_hh[256 + h];
    float r = 1.f / (1.f + expf(-(gir + ghr)));
    float z = 1.f / (1.f + expf(-(giz + ghz)));
    float n = tanhf(fmaf(r, ghn, gin));
    float hv = (1.f - z) * n + z * Hin[row * 128 + h];
    Hout[row * 128 + h] = hv;
    int b = row >> 7, j = row & 127;
    HTdst[(size_t)b * 16384 + h * 128 + j] = hv;
}

// ---- GEMM (split-K 32, 24.5KB smem): C[idx,n,j] = sum_k A[n,k]*HT[idx,k,j]; rb in [0,314) ----
__device__ void gemm_role(int rb, const float* __restrict__ A, long sy,
                          const float* __restrict__ HT, float* __restrict__ C, float* sm) {
    float* As = sm;               // [64][32]  8192B
    float* Hs = sm + 64 * 32;     // [32][132] 16896B
    int idx = rb / 157;
    int rowBase = (rb % 157) * 64;
    const float* Ab = A + (size_t)idx * sy;
    const float* HTb = HT + (size_t)idx * 16384;
    float* Cb = C + (size_t)idx * BATCH;
    int tid = threadIdx.x;
    int c0 = (tid & 15) * 4;
    int r0 = (tid >> 4) * 4;

    unsigned long long aA[4][2], aB[4][2];
    #pragma unroll
    for (int i = 0; i < 4; ++i) { aA[i][0] = aA[i][1] = aB[i][0] = aB[i][1] = 0ull; }

    #pragma unroll
    for (int kh = 0; kh < 4; ++kh) {
        if (kh) __syncthreads();
        for (int i = tid; i < 32 * 128; i += 256) {
            int k = i >> 7, j = i & 127;
            Hs[k * 132 + j] = HTb[(kh * 32 + k) * 128 + j];
        }
        for (int i = tid; i < 64 * 8; i += 256) {
            int r = i >> 3, c4 = i & 7;
            int row = rowBase + r;
            float4 v = (row < NNODE)
                ? __ldg((const float4*)(Ab + (size_t)row * 128 + kh * 32) + c4)
                : make_float4(0.f, 0.f, 0.f, 0.f);
            *((float4*)(As + r * 32) + c4) = v;
        }
        __syncthreads();
        const float* ar = As + r0 * 32;
        #pragma unroll 4
        for (int k = 0; k < 32; ++k) {
            ulonglong2 hA = *(const ulonglong2*)(Hs + k * 132 + c0);
            ulonglong2 hB = *(const ulonglong2*)(Hs + k * 132 + c0 + 64);
            #pragma unroll
            for (int i = 0; i < 4; ++i) {
                unsigned long long ap = pk2(ar[i * 32 + k]);
                FFMA2(aA[i][0], ap, hA.x);
                FFMA2(aA[i][1], ap, hA.y);
                FFMA2(aB[i][0], ap, hB.x);
                FFMA2(aB[i][1], ap, hB.y);
            }
        }
    }
    #pragma unroll
    for (int i = 0; i < 4; ++i) {
        int row = rowBase + r0 + i;
        if (row < NNODE) {
            float2 l0 = up2(aA[i][0]), l1 = up2(aA[i][1]);
            float2 m0 = up2(aB[i][0]), m1 = up2(aB[i][1]);
            *((float4*)(Cb + (size_t)row * 128 + c0)) = make_float4(l0.x, l0.y, l1.x, l1.y);
            *((float4*)(Cb + (size_t)row * 128 + c0 + 64)) = make_float4(m0.x, m0.y, m1.x, m1.y);
        }
    }
}

// ---- propagation: 4 nodes per 256-thread block ----
__device__ void prop_role(int rb, const float* __restrict__ tmp2, float* __restrict__ out2,
                          float* __restrict__ sc2, const float* __restrict__ p1,
                          const float* __restrict__ biasc) {
    int tid = threadIdx.x;
    int sub = tid >> 6;
    int b = (tid >> 5) & 1;
    int q = tid & 31;
    int i = rb * 4 + sub;
    const float* tb = tmp2 + (size_t)b * BATCH;
    int e0 = g_colptr[i], e1 = g_colptr[i + 1];
    float4 acc = make_float4(0.f, 0.f, 0.f, 0.f);

    int e = e0;
    for (; e + 4 <= e1; e += 4) {
        int2 c0v = __ldg(&g_csr[e]);
        int2 c1v = __ldg(&g_csr[e + 1]);
        int2 c2v = __ldg(&g_csr[e + 2]);
        int2 c3v = __ldg(&g_csr[e + 3]);
        float4 r0 = __ldg((const float4*)(tb + (size_t)c0v.x * 128) + q);
        float4 r1 = __ldg((const float4*)(tb + (size_t)c1v.x * 128) + q);
        float4 r2 = __ldg((const float4*)(tb + (size_t)c2v.x * 128) + q);
        float4 r3 = __ldg((const float4*)(tb + (size_t)c3v.x * 128) + q);
        float v0 = __int_as_float(c0v.y), v1 = __int_as_float(c1v.y);
        float v2 = __int_as_float(c2v.y), v3 = __int_as_float(c3v.y);
        acc.x = fmaf(v0, r0.x, acc.x); acc.y = fmaf(v0, r0.y, acc.y);
        acc.z = fmaf(v0, r0.z, acc.z); acc.w = fmaf(v0, r0.w, acc.w);
        acc.x = fmaf(v1, r1.x, acc.x); acc.y = fmaf(v1, r1.y, acc.y);
        acc.z = fmaf(v1, r1.z, acc.z); acc.w = fmaf(v1, r1.w, acc.w);
        acc.x = fmaf(v2, r2.x, acc.x); acc.y = fmaf(v2, r2.y, acc.y);
        acc.z = fmaf(v2, r2.z, acc.z); acc.w = fmaf(v2, r2.w, acc.w);
        acc.x = fmaf(v3, r3.x, acc.x); acc.y = fmaf(v3, r3.y, acc.y);
        acc.z = fmaf(v3, r3.z, acc.z); acc.w = fmaf(v3, r3.w, acc.w);
    }
    for (; e < e1; ++e) {
        int2 sv = __ldg(&g_csr[e]);
        float v = __int_as_float(sv.y);
        float4 r = __ldg((const float4*)(tb + (size_t)sv.x * 128) + q);
        acc.x = fmaf(v, r.x, acc.x); acc.y = fmaf(v, r.y, acc.y);
        acc.z = fmaf(v, r.z, acc.z); acc.w = fmaf(v, r.w, acc.w);
    }
    float di = g_dinv[i];
    size_t soff = (size_t)i * 128;
    float4 sv = __ldg((const float4*)(tb + soff) + q);
    acc.x = fmaf(di, sv.x, acc.x); acc.y = fmaf(di, sv.y, acc.y);
    acc.z = fmaf(di, sv.z, acc.z); acc.w = fmaf(di, sv.w, acc.w);
    float4 bb = __ldg((const float4*)biasc + q);
    float4 o;
    o.x = fmaxf(fmaf(di, acc.x, bb.x), 0.f);
    o.y = fmaxf(fmaf(di, acc.y, bb.y), 0.f);
    o.z = fmaxf(fmaf(di, acc.z, bb.z), 0.f);
    o.w = fmaxf(fmaf(di, acc.w, bb.w), 0.f);
    __stcs((float4*)(out2 + (size_t)b * BATCH + soff) + q, o);
    float4 pv = __ldg((const float4*)p1 + q);
    float s = o.x * pv.x + o.y * pv.y + o.z * pv.z + o.w * pv.w;
    #pragma unroll
    for (int off = 16; off > 0; off >>= 1) s += __shfl_down_sync(0xffffffffu, s, off);
    if (q == 0) sc2[b * NNODE + i] = s / g_pnorm[1];
}

// ================= mega kernel: role dispatch =================
// Order: small roles FIRST (wave-1 overlap with prop), then the 2500 prop blocks.
#define PIPE_SMEM 25088
__global__ void __launch_bounds__(256) pipe_kernel(
        int nProp, const float* pTmp2, float* pOut2, float* pSc2,
        const float* p1, const float* bias0,
        int nGemm, const float* gA, long gSy, const float* gHT, float* gC,
        int nTopk, int topkTbBase, const float* x,
        int nGruA, const float* aXg, const float* aHin, float* aHout, float* aHT,
        const float* aWih, const float* aWhh, const float* aBih, const float* aBhh,
        int nGruB, const float* bXg, const float* bHin, float* bHout, float* bHT,
        const float* bWih, const float* bWhh, const float* bBih, const float* bBhh) {
    extern __shared__ char sm[];
    int rb = blockIdx.x;
    if (rb < nGemm) { gemm_role(rb, gA, gSy, gHT, gC, (float*)sm); return; }
    rb -= nGemm;
    if (rb < nTopk) { topk_role(topkTbBase + rb, 1, x, sm); return; }
    rb -= nTopk;
    if (rb < nGruA) { gru_role(rb, aXg, aHin, aHout, aHT, aWih, aWhh, aBih, aBhh, (float*)sm); return; }
    rb -= nGruA;
    if (rb < nGruB) { gru_role(rb, bXg, bHin, bHout, bHT, bWih, bWhh, bBih, bBhh, (float*)sm); return; }
    rb -= nGruB;
    if (rb < nProp) { prop_role(rb, pTmp2, pOut2, pSc2, p1, bias0); }
}

// standalone layer-0 topk (pre-phase)
__global__ void __launch_bounds__(256) topk0_kernel(const float* __restrict__ x) {
    extern __shared__ char sm[];
    topk_role(blockIdx.x, 0, x, sm);
}

// ---------------- final propagation (2 tb) ----------------
__global__ void __launch_bounds__(64) prop_final_kernel(const float* __restrict__ tmpAll,
                                                        float* __restrict__ dout,
                                                        const float* __restrict__ biasc) {
    __shared__ int2 se[64];
    int i = blockIdx.x;
    int tid = threadIdx.x;
    int b = tid >> 5, q = tid & 31;
    const float* tb = tmpAll + (size_t)b * BATCH;
    int e0 = g_colptr[i], e1 = g_colptr[i + 1];
    float4 acc = make_float4(0.f, 0.f, 0.f, 0.f);

    for (int base = e0; base < e1; base += 64) {
        int m = min(64, e1 - base);
        __syncthreads();
        if (tid < m) se[tid] = g_csr[base + tid];
        __syncthreads();
        #pragma unroll 8
        for (int e = 0; e < m; ++e) {
            int2 sv = se[e];
            float v = __int_as_float(sv.y);
            float4 r = __ldg((const float4*)(tb + (size_t)sv.x * 128) + q);
            acc.x = fmaf(v, r.x, acc.x); acc.y = fmaf(v, r.y, acc.y);
            acc.z = fmaf(v, r.z, acc.z); acc.w = fmaf(v, r.w, acc.w);
        }
    }
    float di = g_dinv[i];
    float4 sv = __ldg((const float4*)(tb + (size_t)i * 128) + q);
    acc.x = fmaf(di, sv.x, acc.x); acc.y = fmaf(di, sv.y, acc.y);
    acc.z = fmaf(di, sv.z, acc.z); acc.w = fmaf(di, sv.w, acc.w);
    float4 bb = __ldg((const float4*)biasc + q);
    float4 o;
    o.x = fmaxf(fmaf(di, acc.x, bb.x), 0.f);
    o.y = fmaxf(fmaf(di, acc.y, bb.y), 0.f);
    o.z = fmaxf(fmaf(di, acc.z, bb.z), 0.f);
    o.w = fmaxf(fmaf(di, acc.w, bb.w), 0.f);
    *((float4*)(dout + (size_t)b * BATCH + (size_t)i * 128) + q) = o;
}

// ---------------- launcher: single-stream software pipeline ----------------
extern "C" void kernel_launch(void* const* d_in, const int* in_sizes, int n_in,
                              void* d_out, int out_size) {
    const float* x   = (const float*)d_in[0];
    const void*  ei  = d_in[1];
    const float* ew  = (const float*)d_in[2];
    const float* W0  = (const float*)d_in[3];
    const float* p   = (const float*)d_in[4];
    const float* wih = (const float*)d_in[5];
    const float* whh = (const float*)d_in[6];
    const float* bih = (const float*)d_in[7];
    const float* bhh = (const float*)d_in[8];
    const float* bias = (const float*)d_in[9];
    float* dout = (float*)d_out;
    int E = in_sizes[2];

    cudaFuncSetAttribute(pipe_kernel, cudaFuncAttributeMaxDynamicSharedMemorySize, PIPE_SMEM);

    float *pH0A, *pH0B, *pH1A, *pH1B, *pHT0, *pHT1, *pP0, *pP1, *pTmp, *pOut0, *pSc1;
    cudaGetSymbolAddress((void**)&pH0A, g_H0A);
    cudaGetSymbolAddress((void**)&pH0B, g_H0B);
    cudaGetSymbolAddress((void**)&pH1A, g_H1A);
    cudaGetSymbolAddress((void**)&pH1B, g_H1B);
    cudaGetSymbolAddress((void**)&pHT0, g_HT0All);
    cudaGetSymbolAddress((void**)&pHT1, g_HT1);
    cudaGetSymbolAddress((void**)&pP0, g_pooled0);
    cudaGetSymbolAddress((void**)&pP1, g_pooled1All);
    cudaGetSymbolAddress((void**)&pTmp, g_tmpAll);
    cudaGetSymbolAddress((void**)&pOut0, g_out0All);
    cudaGetSymbolAddress((void**)&pSc1, g_scores1All);

    // ---- pre-phase ----
    init_kernel<<<256, 256>>>((const int*)ei, E, p, W0);
    deg_kernel<<<(E + 255) / 256, 256>>>(ei, ew, E);
    scan_kernel<<<1, 256>>>();
    fill_kernel<<<(E + 255) / 256, 256>>>(ei, ew, E);
    scores0_kernel<<<(NT * NB * NNODE + 7) / 8, 256>>>(x, p);
    topk0_kernel<<<16, 256, TOPK_SMEM>>>(x);

    // ---- software pipeline: L(t) = gemm(t) | topk1(t-2) | gru0(t+1) | gru1(t-3) | prop(t-1) ----
    for (int t = -1; t <= 10; ++t) {
        int pt = t - 1, kt = t - 2, sA = t + 1, sB = t - 3;
        int nProp = (pt >= 0 && pt <= 7) ? 2500 : 0;
        int nGemm = (t >= 0 && t <= 7) ? 314 : 0;
        int nTopk = (kt >= 0 && kt <= 7) ? 2 : 0;
        int nGruA = (sA >= 1 && sA <= 7) ? 128 : 0;
        if (t == -1) { nGruA = 128; sA = 0; }          // gru0(0)
        int nGruB = (sB >= 0 && sB <= 7) ? 128 : 0;
        int total = nProp + nGemm + nTopk + nGruA + nGruB;
        if (total == 0) continue;
        int ptc = pt < 0 ? 0 : (pt > 7 ? 7 : pt);
        int ktc = kt < 0 ? 0 : (kt > 7 ? 7 : kt);
        int tc  = t  < 0 ? 0 : (t  > 7 ? 7 : t);
        int sAc = sA < 0 ? 0 : (sA > 7 ? 7 : sA);
        int sBc = sB < 0 ? 0 : (sB > 7 ? 7 : sB);
        pipe_kernel<<<total, 256, PIPE_SMEM>>>(
            nProp, pTmp + (size_t)ptc * NB * BATCH, pOut0 + (size_t)ptc * NB * BATCH,
            pSc1 + (size_t)ptc * NB * NNODE, p + 128, bias,
            nGemm, x + (size_t)tc * BATCH, (long)NT * BATCH,
            pHT0 + (size_t)tc * NB * 16384, pTmp + (size_t)tc * NB * BATCH,
            nTopk, ktc * 2, x,
            nGruA, pP0 + (size_t)sAc * 32768,
            (sAc & 1) ? pH0B : pH0A, (sAc & 1) ? pH0A : pH0B,
            pHT0 + (size_t)sAc * NB * 16384, wih, whh, bih, bhh,
            nGruB, pP1 + (size_t)sBc * 32768,
            (sBc & 1) ? pH1B : pH1A, (sBc & 1) ? pH1A : pH1B,
            pHT1, wih + 49152, whh + 49152, bih + 384, bhh + 384);
    }

    // ---- final layer-1 GEMM (t=7) + propagation to output ----
    pipe_kernel<<<314, 256, PIPE_SMEM>>>(
        0, pTmp, pOut0, pSc1, p + 128, bias,
        314, pOut0 + (size_t)14 * BATCH, (long)BATCH, pHT1, pTmp,
        0, 0, x,
        0, pP0, pH0A, pH0B, pHT0, wih, whh, bih, bhh,
        0, pP1, pH1A, pH1B, pHT1, wih + 49152, whh + 49152, bih + 384, bhh + 384);
    prop_final_kernel<<<NNODE, 64>>>(pTmp, dout, bias + 128);
}

// round 16
// speedup vs baseline: 1.3048x; 1.0475x over previous
#include <cuda_runtime.h>
#include <cuda_bf16.h>
#include <math.h>

#define NNODE 10000
#define FDIM  128
#define NB    2
#define NT    8
#define EMAX  321000
#define BATCH (NNODE * FDIM)

// ---------------- device scratch ----------------
__device__ int   g_e64;
__device__ float g_deg[NNODE];
__device__ float g_dinv[NNODE];
__device__ int   g_counts[NNODE];
__device__ int   g_colptr[NNODE + 1];
__device__ int   g_cursor[NNODE];
__device__ int2  g_csr[EMAX];                 // {src, val bits}
__device__ float g_pnorm[2];
__device__ float g_scores0[NT * NB * NNODE];
__device__ float g_scores1All[NT * NB * NNODE];
__device__ __align__(16) float g_pooled0[NT * NB * 16384];
__device__ __align__(16) float g_pooled1All[NT * NB * 16384];
__device__ __align__(16) float g_H0A[NB * 16384];
__device__ __align__(16) float g_H0B[NB * 16384];
__device__ __align__(16) float g_H1A[NB * 16384];
__device__ __align__(16) float g_H1B[NB * 16384];
__device__ __align__(16) float g_HT0All[NT * NB * 16384];  // [t][b][k][j]
__device__ __align__(16) float g_HT1[NB * 16384];
__device__ __align__(16) float g_PxAll[NT * NB * BATCH];   // raw P*x, 82 MB (also holds P*out0_7 at [0..2B))
__device__ __align__(16) float g_out0All[NT * NB * BATCH]; // 82 MB

__device__ __forceinline__ void read_edge(const void* ei, int e, int E, int& s, int& t) {
    if (g_e64) {
        const long long* p = (const long long*)ei;
        s = (int)p[e]; t = (int)p[E + e];
    } else {
        const int* p = (const int*)ei;
        s = p[e]; t = p[E + e];
    }
}

__device__ __forceinline__ unsigned int fkey(float f) {
    unsigned int b = __float_as_uint(f);
    return (b & 0x80000000u) ? ~b : (b | 0x80000000u);
}

__device__ __forceinline__ unsigned long long pk2(float v) {
    unsigned long long r;
    asm("mov.b64 %0, {%1, %1};" : "=l"(r) : "f"(v));
    return r;
}
__device__ __forceinline__ float2 up2(unsigned long long v) {
    float2 r;
    asm("mov.b64 {%0, %1}, %2;" : "=f"(r.x), "=f"(r.y) : "l"(v));
    return r;
}
#define FFMA2(acc, a, b) asm("fma.rn.f32x2 %0, %1, %2, %0;" : "+l"(acc) : "l"(a), "l"(b))

// ---------------- preprocessing ----------------
__global__ void init_kernel(const int* ei32, int E,
                            const float* __restrict__ p,
                            const float* __restrict__ W0) {
    int gid = blockIdx.x * 256 + threadIdx.x;
    if (gid < NNODE) { g_deg[gid] = 0.f; g_counts[gid] = 0; }
    if (gid < 65536) {
        int c = gid >> 15;
        int b = (gid >> 14) & 1;
        int ji = gid & 16383;
        int j = ji >> 7, i2 = ji & 127;
        float v = W0[c * 16384 + i2 * 128 + j];   // H[c][b][j][i] = W0[c][i][j]
        float* H = (c == 0) ? g_H0A : g_H1A;
        H[b * 16384 + ji] = v;
    }
    if (blockIdx.x == 255) {
        __shared__ int any;
        if (threadIdx.x == 0) any = 0;
        __syncthreads();
        int lim = min(2048, E / 2);
        for (int i = threadIdx.x; i < lim; i += 256)
            if (ei32[2 * i + 1] != 0) any = 1;
        __syncthreads();
        if (threadIdx.x == 0) g_e64 = (any == 0) ? 1 : 0;
    }
    if (blockIdx.x == 254 && threadIdx.x < 64) {
        int w = threadIdx.x >> 5, l = threadIdx.x & 31;
        const float* pc = p + w * 128;
        float s = 0.f;
        for (int i = l; i < 128; i += 32) { float v = pc[i]; s += v * v; }
        #pragma unroll
        for (int o = 16; o > 0; o >>= 1) s += __shfl_down_sync(0xffffffffu, s, o);
        if (l == 0) g_pnorm[w] = sqrtf(s);
    }
}

// deg (blocks 0..1249) merged with scores0 (rest)
__global__ void deg_scores0_kernel(const void* ei, const float* __restrict__ ew, int E,
                                   const float* __restrict__ x, const float* __restrict__ p0) {
    if (blockIdx.x < 1250) {
        int e = blockIdx.x * 256 + threadIdx.x;
        if (e >= E) return;
        int s, t;
        read_edge(ei, e, E, s, t);
        atomicAdd(&g_deg[t], ew[e]);
        atomicAdd(&g_counts[t], 1);
        return;
    }
    int wid = ((blockIdx.x - 1250) << 3) + (threadIdx.x >> 5);
    if (wid >= NT * NB * NNODE) return;
    int lane = threadIdx.x & 31;
    int t = wid / (NB * NNODE);
    int rem = wid - t * (NB * NNODE);
    int b = rem / NNODE;
    int n = rem - b * NNODE;
    const float* xr = x + (((size_t)(b * NT + t)) * NNODE + n) * FDIM;
    float4 v = __ldg((const float4*)xr + lane);
    float4 pv = __ldg((const float4*)p0 + lane);
    float s = v.x * pv.x + v.y * pv.y + v.z * pv.z + v.w * pv.w;
    #pragma unroll
    for (int o = 16; o > 0; o >>= 1) s += __shfl_down_sync(0xffffffffu, s, o);
    if (lane == 0) g_scores0[wid] = s / g_pnorm[0];
}

__global__ void scan_kernel() {
    __shared__ int part[256];
    int tid = threadIdx.x;
    int start = tid * 40;
    int s = 0;
    for (int j = 0; j < 40; ++j) {
        int idx = start + j;
        if (idx < NNODE) s += g_counts[idx];
    }
    part[tid] = s;
    __syncthreads();
    for (int off = 1; off < 256; off <<= 1) {
        int v = (tid >= off) ? part[tid - off] : 0;
        __syncthreads();
        part[tid] += v;
        __syncthreads();
    }
    int run = part[tid] - s;
    for (int j = 0; j < 40; ++j) {
        int idx = start + j;
        if (idx < NNODE) {
            g_colptr[idx] = run; g_cursor[idx] = run;
            run += g_counts[idx];
            g_dinv[idx] = rsqrtf(g_deg[idx] + 1.0f);
        }
    }
    if (tid == 255) g_colptr[NNODE] = part[255];
}

// ================= roles (256-thread) =================

// ---- top-k 128 of 10000 + pool; tb = t*2+b ----
#define TKCAP 1024
#define TOPK_SMEM 21760
__device__ void topk_role(int tb, int mode, const float* __restrict__ x, char* smraw) {
    int* histW = (int*)smraw;
    unsigned int* cKey = (unsigned int*)(smraw + 8192);
    int* cIdx = (int*)(smraw + 12288);
    float* cVal = (float*)(smraw + 16384);
    int* rIdx = (int*)(smraw + 20480);
    float* rTanh = (float*)(smraw + 20992);
    int* scl = (int*)(smraw + 21504);

    int tid = threadIdx.x;
    int grp = tid >> 5;

    const float* sc;
    const float* feat;
    float* pool;
    if (mode == 0) {
        int t = tb >> 1, b = tb & 1;
        sc = g_scores0 + (size_t)tb * NNODE;
        feat = x + ((size_t)(b * NT + t)) * BATCH;
        pool = g_pooled0 + (size_t)tb * 16384;
    } else {
        sc = g_scores1All + (size_t)tb * NNODE;
        feat = g_out0All + (size_t)tb * BATCH;
        pool = g_pooled1All + (size_t)tb * 16384;
    }

    unsigned int prefix = 0, pmask = 0;
    int K = 128;
    for (int shift = 24; shift >= 0; shift -= 8) {
        for (int i = tid; i < 8 * 256; i += 256) histW[i] = 0;
        __syncthreads();
        for (int n = tid; n < NNODE; n += 256) {
            unsigned int kk = fkey(sc[n]);
            if ((kk & pmask) == prefix) atomicAdd(&histW[grp * 256 + ((kk >> shift) & 255)], 1);
        }
        __syncthreads();
        {
            int s = 0;
            #pragma unroll
            for (int g = 0; g < 8; ++g) s += histW[g * 256 + tid];
            __syncthreads();
            histW[tid] = s;
        }
        __syncthreads();
        if (tid == 0) {
            int cum = 0, bsel = 0;
            for (int bkt = 255; bkt >= 0; --bkt) {
                int h = histW[bkt];
                if (cum + h >= K) { bsel = bkt; break; }
                cum += h;
            }
            scl[1] = bsel; scl[2] = cum;
        }
        __syncthreads();
        prefix |= ((unsigned int)scl[1]) << shift;
        pmask |= 0xFFu << shift;
        K -= scl[2];
        __syncthreads();
    }
    if (tid == 0) scl[0] = 0;
    __syncthreads();
    for (int n = tid; n < NNODE; n += 256) {
        float v = sc[n];
        unsigned int kk = fkey(v);
        if (kk >= prefix) {
            int pos = atomicAdd(&scl[0], 1);
            if (pos < TKCAP) { cKey[pos] = kk; cIdx[pos] = n; cVal[pos] = v; }
        }
    }
    __syncthreads();
    int C = min(scl[0], TKCAP);
    for (int i = tid; i < C; i += 256) {
        unsigned int ki = cKey[i];
        int ii = cIdx[i];
        int rank = 0;
        for (int j = 0; j < C; ++j) {
            unsigned int kj = cKey[j];
            rank += (kj > ki) || (kj == ki && cIdx[j] < ii);
        }
        if (rank < 128) { rIdx[rank] = ii; rTanh[rank] = tanhf(cVal[i]); }
    }
    __syncthreads();
    for (int i = tid; i < 4096; i += 256) {
        int row = i >> 5, q = i & 31;
        float4 v = __ldg((const float4*)(feat + (size_t)rIdx[row] * FDIM) + q);
        float s = rTanh[row];
        v.x *= s; v.y *= s; v.z *= s; v.w *= s;
        *((float4*)(pool + row * 128) + q) = v;
    }
}

// ---- GRU step; rb in [0,128) ----
__device__ void gru_role(int rb,
                         const float* __restrict__ xg, const float* __restrict__ Hin,
                         float* __restrict__ Hout, float* __restrict__ HTdst,
                         const float* __restrict__ w_ih, const float* __restrict__ w_hh,
                         const float* __restrict__ b_ih, const float* __restrict__ b_hh,
                         float* sm) {
    float* xs = sm;
    float* hs = sm + 528;
    float* wi = sm + 1056;
    float* wh = sm + 2640;
    int tid = threadIdx.x;
    int r0 = (rb & 15) * 16;
    int h0 = (rb >> 4) * 16;
    int hh = tid & 15, rr = tid >> 4;
    float acc[6] = {0.f, 0.f, 0.f, 0.f, 0.f, 0.f};

    for (int kc = 0; kc < 128; kc += 32) {
        for (int i = tid; i < 512; i += 256) {
            int r = i >> 5, k = i & 31;
            xs[r * 33 + k] = xg[(r0 + r) * 128 + kc + k];
            hs[r * 33 + k] = Hin[(r0 + r) * 128 + kc + k];
        }
        #pragma unroll
        for (int g = 0; g < 3; ++g)
            for (int i = tid; i < 512; i += 256) {
                int r = i >> 5, k = i & 31;
                wi[g * 528 + r * 33 + k] = w_ih[(g * 128 + h0 + r) * 128 + kc + k];
                wh[g * 528 + r * 33 + k] = w_hh[(g * 128 + h0 + r) * 128 + kc + k];
            }
        __syncthreads();
        #pragma unroll
        for (int k = 0; k < 32; ++k) {
            float xv = xs[rr * 33 + k], hv = hs[rr * 33 + k];
            acc[0] = fmaf(xv, wi[0 * 528 + hh * 33 + k], acc[0]);
            acc[1] = fmaf(xv, wi[1 * 528 + hh * 33 + k], acc[1]);
            acc[2] = fmaf(xv, wi[2 * 528 + hh * 33 + k], acc[2]);
            acc[3] = fmaf(hv, wh[0 * 528 + hh * 33 + k], acc[3]);
            acc[4] = fmaf(hv, wh[1 * 528 + hh * 33 + k], acc[4]);
            acc[5] = fmaf(hv, wh[2 * 528 + hh * 33 + k], acc[5]);
        }
        __syncthreads();
    }
    int row = r0 + rr, h = h0 + hh;
    float gir = acc[0] + b_ih[h], giz = acc[1] + b_ih[128 + h], gin = acc[2] + b_ih[256 + h];
    float ghr = acc[3] + b_hh[h], ghz = acc[4] + b_hh[128 + h], ghn = acc[5] + b_hh[256 + h];
    float r = 1.f / (1.f + expf(-(gir + ghr)));
    float z = 1.f / (1.f + expf(-(giz + ghz)));
    float n = tanhf(fmaf(r, ghn, gin));
    float hv = (1.f - z) * n + z * Hin[row * 128 + h];
    Hout[row * 128 + h] = hv;
    int b = row >> 7, j = row & 127;
    HTdst[(size_t)b * 16384 + h * 128 + j] = hv;
}

// ---- GEMM (split-K 32) + fused bias + relu + optional scores1 epilogue ----
// C[idx,n,j] = relu( sum_k A[n,k]*HT[idx,k,j] + bias[j] ); rb in [0,314)
__device__ void gemm_role(int rb, const float* __restrict__ A, long sy,
                          const float* __restrict__ HT, float* __restrict__ C,
                          const float* __restrict__ biasc,
                          float* __restrict__ scores, const float* __restrict__ p1,
                          float* sm) {
    float* As = sm;               // [64][32]
    float* Hs = sm + 64 * 32;     // [32][132]
    int idx = rb / 157;
    int rowBase = (rb % 157) * 64;
    const float* Ab = A + (size_t)idx * sy;
    const float* HTb = HT + (size_t)idx * 16384;
    float* Cb = C + (size_t)idx * BATCH;
    float* scb = scores ? (scores + (size_t)idx * NNODE) : (float*)0;
    int tid = threadIdx.x;
    int c0 = (tid & 15) * 4;
    int r0 = (tid >> 4) * 4;

    unsigned long long aA[4][2], aB[4][2];
    #pragma unroll
    for (int i = 0; i < 4; ++i) { aA[i][0] = aA[i][1] = aB[i][0] = aB[i][1] = 0ull; }

    #pragma unroll
    for (int kh = 0; kh < 4; ++kh) {
        if (kh) __syncthreads();
        for (int i = tid; i < 32 * 128; i += 256) {
            int k = i >> 7, j = i & 127;
            Hs[k * 132 + j] = HTb[(kh * 32 + k) * 128 + j];
        }
        for (int i = tid; i < 64 * 8; i += 256) {
            int r = i >> 3, c4 = i & 7;
            int row = rowBase + r;
            float4 v = (row < NNODE)
                ? __ldg((const float4*)(Ab + (size_t)row * 128 + kh * 32) + c4)
                : make_float4(0.f, 0.f, 0.f, 0.f);
            *((float4*)(As + r * 32) + c4) = v;
        }
        __syncthreads();
        const float* ar = As + r0 * 32;
        #pragma unroll 4
        for (int k = 0; k < 32; ++k) {
            ulonglong2 hA = *(const ulonglong2*)(Hs + k * 132 + c0);
            ulonglong2 hB = *(const ulonglong2*)(Hs + k * 132 + c0 + 64);
            #pragma unroll
            for (int i = 0; i < 4; ++i) {
                unsigned long long ap = pk2(ar[i * 32 + k]);
                FFMA2(aA[i][0], ap, hA.x);
                FFMA2(aA[i][1], ap, hA.y);
                FFMA2(aB[i][0], ap, hB.x);
                FFMA2(aB[i][1], ap, hB.y);
            }
        }
    }
    // epilogue: bias + relu (+ scores)
    float4 bb0 = __ldg((const float4*)(biasc + c0));
    float4 bb1 = __ldg((const float4*)(biasc + c0 + 64));
    float4 pv0 = make_float4(0.f, 0.f, 0.f, 0.f), pv1 = pv0;
    if (scb) {
        pv0 = __ldg((const float4*)(p1 + c0));
        pv1 = __ldg((const float4*)(p1 + c0 + 64));
    }
    float pinv = scb ? (1.f / g_pnorm[1]) : 0.f;
    #pragma unroll
    for (int i = 0; i < 4; ++i) {
        int row = rowBase + r0 + i;
        float2 l0 = up2(aA[i][0]), l1 = up2(aA[i][1]);
        float2 m0 = up2(aB[i][0]), m1 = up2(aB[i][1]);
        float o0 = fmaxf(l0.x + bb0.x, 0.f), o1 = fmaxf(l0.y + bb0.y, 0.f);
        float o2 = fmaxf(l1.x + bb0.z, 0.f), o3 = fmaxf(l1.y + bb0.w, 0.f);
        float o4 = fmaxf(m0.x + bb1.x, 0.f), o5 = fmaxf(m0.y + bb1.y, 0.f);
        float o6 = fmaxf(m1.x + bb1.z, 0.f), o7 = fmaxf(m1.y + bb1.w, 0.f);
        if (row < NNODE) {
            *((float4*)(Cb + (size_t)row * 128 + c0)) = make_float4(o0, o1, o2, o3);
            *((float4*)(Cb + (size_t)row * 128 + c0 + 64)) = make_float4(o4, o5, o6, o7);
        }
        if (scb) {
            float s = o0 * pv0.x + o1 * pv0.y + o2 * pv0.z + o3 * pv0.w
                    + o4 * pv1.x + o5 * pv1.y + o6 * pv1.z + o7 * pv1.w;
            #pragma unroll
            for (int off = 8; off > 0; off >>= 1)
                s += __shfl_down_sync(0xffffffffu, s, off, 16);
            if ((tid & 15) == 0 && row < NNODE) scb[row] = s * pinv;
        }
    }
}

// ---- RAW propagation (P * src): 4 nodes per block, no bias/relu ----
__device__ void prop_role(int rb, const float* __restrict__ src, long srcStride,
                          float* __restrict__ dst, long dstStride) {
    int tid = threadIdx.x;
    int sub = tid >> 6;
    int b = (tid >> 5) & 1;
    int q = tid & 31;
    int i = rb * 4 + sub;
    const float* tb = src + (size_t)b * srcStride;
    int e0 = g_colptr[i], e1 = g_colptr[i + 1];
    float4 acc = make_float4(0.f, 0.f, 0.f, 0.f);

    int e = e0;
    for (; e + 4 <= e1; e += 4) {
        int2 c0v = __ldg(&g_csr[e]);
        int2 c1v = __ldg(&g_csr[e + 1]);
        int2 c2v = __ldg(&g_csr[e + 2]);
        int2 c3v = __ldg(&g_csr[e + 3]);
        float4 r0 = __ldg((const float4*)(tb + (size_t)c0v.x * 128) + q);
        float4 r1 = __ldg((const float4*)(tb + (size_t)c1v.x * 128) + q);
        float4 r2 = __ldg((const float4*)(tb + (size_t)c2v.x * 128) + q);
        float4 r3 = __ldg((const float4*)(tb + (size_t)c3v.x * 128) + q);
        float v0 = __int_as_float(c0v.y), v1 = __int_as_float(c1v.y);
        float v2 = __int_as_float(c2v.y), v3 = __int_as_float(c3v.y);
        acc.x = fmaf(v0, r0.x, acc.x); acc.y = fmaf(v0, r0.y, acc.y);
        acc.z = fmaf(v0, r0.z, acc.z); acc.w = fmaf(v0, r0.w, acc.w);
        acc.x = fmaf(v1, r1.x, acc.x); acc.y = fmaf(v1, r1.y, acc.y);
        acc.z = fmaf(v1, r1.z, acc.z); acc.w = fmaf(v1, r1.w, acc.w);
        acc.x = fmaf(v2, r2.x, acc.x); acc.y = fmaf(v2, r2.y, acc.y);
        acc.z = fmaf(v2, r2.z, acc.z); acc.w = fmaf(v2, r2.w, acc.w);
        acc.x = fmaf(v3, r3.x, acc.x); acc.y = fmaf(v3, r3.y, acc.y);
        acc.z = fmaf(v3, r3.z, acc.z); acc.w = fmaf(v3, r3.w, acc.w);
    }
    for (; e < e1; ++e) {
        int2 sv = __ldg(&g_csr[e]);
        float v = __int_as_float(sv.y);
        float4 r = __ldg((const float4*)(tb + (size_t)sv.x * 128) + q);
        acc.x = fmaf(v, r.x, acc.x); acc.y = fmaf(v, r.y, acc.y);
        acc.z = fmaf(v, r.z, acc.z); acc.w = fmaf(v, r.w, acc.w);
    }
    float di = g_dinv[i];
    size_t soff = (size_t)i * 128;
    float4 sv = __ldg((const float4*)(tb + soff) + q);
    acc.x = fmaf(di, sv.x, acc.x); acc.y = fmaf(di, sv.y, acc.y);
    acc.z = fmaf(di, sv.z, acc.z); acc.w = fmaf(di, sv.w, acc.w);
    float4 o;
    o.x = di * acc.x; o.y = di * acc.y; o.z = di * acc.z; o.w = di * acc.w;
    *((float4*)(dst + (size_t)b * dstStride + soff) + q) = o;
}

// ================= mega kernel: role dispatch (small roles first) =================
#define PIPE_SMEM 25088
__global__ void __launch_bounds__(256) pipe_kernel(
        int nGemm, const float* gA, long gSy, const float* gHT, float* gC,
        const float* gBias, float* gScores, const float* gP1,
        int nTopk, int topkTbBase, const float* x,
        int nGruA, const float* aXg, const float* aHin, float* aHout, float* aHT,
        const float* aWih, const float* aWhh, const float* aBih, const float* aBhh,
        int nGruB, const float* bXg, const float* bHin, float* bHout, float* bHT,
        const float* bWih, const float* bWhh, const float* bBih, const float* bBhh,
        int nProp, const float* pSrc, long pSrcStride, float* pDst, long pDstStride) {
    extern __shared__ char sm[];
    int rb = blockIdx.x;
    if (rb < nGemm) { gemm_role(rb, gA, gSy, gHT, gC, gBias, gScores, gP1, (float*)sm); return; }
    rb -= nGemm;
    if (rb < nTopk) { topk_role(topkTbBase + rb, 1, x, sm); return; }
    rb -= nTopk;
    if (rb < nGruA) { gru_role(rb, aXg, aHin, aHout, aHT, aWih, aWhh, aBih, aBhh, (float*)sm); return; }
    rb -= nGruA;
    if (rb < nGruB) { gru_role(rb, bXg, bHin, bHout, bHT, bWih, bWhh, bBih, bBhh, (float*)sm); return; }
    rb -= nGruB;
    if (rb < nProp) { prop_role(rb, pSrc, pSrcStride, pDst, pDstStride); }
}

// fill (CSR) merged with layer-0 topk
__global__ void __launch_bounds__(256) fill_topk0_kernel(const void* ei,
                                                         const float* __restrict__ ew, int E,
                                                         const float* __restrict__ x) {
    extern __shared__ char sm[];
    if (blockIdx.x < 16) { topk_role(blockIdx.x, 0, x, sm); return; }
    int e = (blockIdx.x - 16) * 256 + threadIdx.x;
    if (e >= E) return;
    int s, t;
    read_edge(ei, e, E, s, t);
    int pos = atomicAdd(&g_cursor[t], 1);
    g_csr[pos] = make_int2(s, __float_as_int(g_dinv[s] * ew[e]));
}

// ---------------- launcher ----------------
extern "C" void kernel_launch(void* const* d_in, const int* in_sizes, int n_in,
                              void* d_out, int out_size) {
    const float* x   = (const float*)d_in[0];
    const void*  ei  = d_in[1];
    const float* ew  = (const float*)d_in[2];
    const float* W0  = (const float*)d_in[3];
    const float* p   = (const float*)d_in[4];
    const float* wih = (const float*)d_in[5];
    const float* whh = (const float*)d_in[6];
    const float* bih = (const float*)d_in[7];
    const float* bhh = (const float*)d_in[8];
    const float* bias = (const float*)d_in[9];
    float* dout = (float*)d_out;
    int E = in_sizes[2];

    cudaFuncSetAttribute(pipe_kernel, cudaFuncAttributeMaxDynamicSharedMemorySize, PIPE_SMEM);
    cudaFuncSetAttribute(fill_topk0_kernel, cudaFuncAttributeMaxDynamicSharedMemorySize, TOPK_SMEM);

    float *pH0A, *pH0B, *pH1A, *pH1B, *pHT0, *pHT1, *pP0, *pP1, *pPx, *pOut0, *pSc1;
    cudaGetSymbolAddress((void**)&pH0A, g_H0A);
    cudaGetSymbolAddress((void**)&pH0B, g_H0B);
    cudaGetSymbolAddress((void**)&pH1A, g_H1A);
    cudaGetSymbolAddress((void**)&pH1B, g_H1B);
    cudaGetSymbolAddress((void**)&pHT0, g_HT0All);
    cudaGetSymbolAddress((void**)&pHT1, g_HT1);
    cudaGetSymbolAddress((void**)&pP0, g_pooled0);
    cudaGetSymbolAddress((void**)&pP1, g_pooled1All);
    cudaGetSymbolAddress((void**)&pPx, g_PxAll);
    cudaGetSymbolAddress((void**)&pOut0, g_out0All);
    cudaGetSymbolAddress((void**)&pSc1, g_scores1All);

    const float* p1 = p + 128;
    const float* wih1 = wih + 49152;
    const float* whh1 = whh + 49152;
    const float* bih1 = bih + 384;
    const float* bhh1 = bhh + 384;

    // ---- pre-phase (4 launches) ----
    init_kernel<<<256, 256>>>((const int*)ei, E, p, W0);
    deg_scores0_kernel<<<1250 + 20000, 256>>>(ei, ew, E, x, p);
    scan_kernel<<<1, 256>>>();
    fill_topk0_kernel<<<16 + 1250, 256, TOPK_SMEM>>>(ei, ew, E, x);

    // ---- pipeline: L(t) = gemm(t-1) | topk1(t-2) | gru0(t) | gru1(t-3) | prop_x(t) ----
    for (int t = 0; t < 8; ++t) {
        int gt = (t >= 1) ? (t - 1) : 0;
        int kt = (t >= 2) ? (t - 2) : 0;
        int sB = (t >= 3) ? (t - 3) : 0;
        int nGemm = (t >= 1) ? 314 : 0;
        int nTopk = (t >= 2) ? 2 : 0;
        int nGruB = (t >= 3) ? 128 : 0;
        int total = nGemm + nTopk + 128 + nGruB + 2500;
        pipe_kernel<<<total, 256, PIPE_SMEM>>>(
            nGemm, pPx + (size_t)gt * 2 * BATCH, (long)BATCH,
            pHT0 + (size_t)gt * NB * 16384, pOut0 + (size_t)gt * 2 * BATCH,
            bias, pSc1 + (size_t)gt * 2 * NNODE, p1,
            nTopk, kt * 2, x,
            128, pP0 + (size_t)t * 32768,
            (t & 1) ? pH0B : pH0A, (t & 1) ? pH0A : pH0B,
            pHT0 + (size_t)t * NB * 16384, wih, whh, bih, bhh,
            nGruB, pP1 + (size_t)sB * 32768,
            (sB & 1) ? pH1B : pH1A, (sB & 1) ? pH1A : pH1B,
            pHT1, wih1, whh1, bih1, bhh1,
            2500, x + (size_t)t * BATCH, (long)NT * BATCH,
            pPx + (size_t)t * 2 * BATCH, (long)BATCH);
    }
    // L8: gemm(7) + topk1(6) + gru1(5)
    pipe_kernel<<<314 + 2 + 128, 256, PIPE_SMEM>>>(
        314, pPx + (size_t)14 * BATCH, (long)BATCH,
        pHT0 + (size_t)7 * NB * 16384, pOut0 + (size_t)14 * BATCH,
        bias, pSc1 + (size_t)14 * NNODE, p1,
        2, 12, x,
        0, pP0, pH0A, pH0B, pHT0, wih, whh, bih, bhh,
        128, pP1 + (size_t)5 * 32768, pH1B, pH1A, pHT1, wih1, whh1, bih1, bhh1,
        0, x, 0L, pPx, 0L);
    // L9: topk1(7) + gru1(6) + prop_final (P * out0_7 -> pPx[0..2B))
    pipe_kernel<<<2 + 128 + 2500, 256, PIPE_SMEM>>>(
        0, pPx, (long)BATCH, pHT0, pOut0, bias, (float*)0, p1,
        2, 14, x,
        0, pP0, pH0A, pH0B, pHT0, wih, whh, bih, bhh,
        128, pP1 + (size_t)6 * 32768, pH1A, pH1B, pHT1, wih1, whh1, bih1, bhh1,
        2500, pOut0 + (size_t)14 * BATCH, (long)BATCH, pPx, (long)BATCH);
    // L10: gru1(7)
    pipe_kernel<<<128, 256, PIPE_SMEM>>>(
        0, pPx, (long)BATCH, pHT0, pOut0, bias, (float*)0, p1,
        0, 0, x,
        0, pP0, pH0A, pH0B, pHT0, wih, whh, bih, bhh,
        128, pP1 + (size_t)7 * 32768, pH1B, pH1A, pHT1, wih1, whh1, bih1, bhh1,
        0, x, 0L, pPx, 0L);
    // L11: gemm_final: relu((P out0_7) @ W1_7 + bias1) -> dout
    pipe_kernel<<<314, 256, PIPE_SMEM>>>(
        314, pPx, (long)BATCH, pHT1, dout, bias + 128, (float*)0, p1,
        0, 0, x,
        0, pP0, pH0A, pH0B, pHT0, wih, whh, bih, bhh,
        0, pP1, pH1A, pH1B, pHT1, wih1, whh1, bih1, bhh1,
        0, x, 0L, pPx, 0L);
}

// round 17
// speedup vs baseline: 1.3223x; 1.0134x over previous
#include <cuda_runtime.h>
#include <cuda_bf16.h>
#include <math.h>

#define NNODE 10000
#define FDIM  128
#define NB    2
#define NT    8
#define EMAX  321000
#define BATCH (NNODE * FDIM)

// ---------------- device scratch ----------------
__device__ int   g_e64;
__device__ float g_deg[NNODE];
__device__ float g_dinv[NNODE];
__device__ int   g_counts[NNODE];
__device__ int   g_colptr[NNODE + 1];
__device__ int   g_cursor[NNODE];
__device__ int2  g_csr[EMAX];                 // {src, val bits}
__device__ float g_pnorm[2];
__device__ float g_scores0[NT * NB * NNODE];
__device__ float g_scores1All[NT * NB * NNODE];
__device__ __align__(16) float g_pooled0[NT * NB * 16384];
__device__ __align__(16) float g_pooled1All[NT * NB * 16384];
__device__ __align__(16) float g_H0A[NB * 16384];
__device__ __align__(16) float g_H0B[NB * 16384];
__device__ __align__(16) float g_H1A[NB * 16384];
__device__ __align__(16) float g_H1B[NB * 16384];
__device__ __align__(16) float g_HT0All[NT * NB * 16384];  // [t][b][k][j]
__device__ __align__(16) float g_HT1[NB * 16384];
__device__ __align__(16) float g_PxAll[NT * NB * BATCH];   // raw P*x (also P*out0_7 at [0..2B))
__device__ __align__(16) float g_out0All[NT * NB * BATCH];

__device__ __forceinline__ void read_edge(const void* ei, int e, int E, int& s, int& t) {
    if (g_e64) {
        const long long* p = (const long long*)ei;
        s = (int)p[e]; t = (int)p[E + e];
    } else {
        const int* p = (const int*)ei;
        s = p[e]; t = p[E + e];
    }
}

__device__ __forceinline__ unsigned int fkey(float f) {
    unsigned int b = __float_as_uint(f);
    return (b & 0x80000000u) ? ~b : (b | 0x80000000u);
}

__device__ __forceinline__ unsigned long long pk2(float v) {
    unsigned long long r;
    asm("mov.b64 %0, {%1, %1};" : "=l"(r) : "f"(v));
    return r;
}
__device__ __forceinline__ float2 up2(unsigned long long v) {
    float2 r;
    asm("mov.b64 {%0, %1}, %2;" : "=f"(r.x), "=f"(r.y) : "l"(v));
    return r;
}
#define FFMA2(acc, a, b) asm("fma.rn.f32x2 %0, %1, %2, %0;" : "+l"(acc) : "l"(a), "l"(b))

// ---------------- preprocessing ----------------
__global__ void init_kernel(const int* ei32, int E,
                            const float* __restrict__ p,
                            const float* __restrict__ W0) {
    int gid = blockIdx.x * 256 + threadIdx.x;
    if (gid < NNODE) { g_deg[gid] = 0.f; g_counts[gid] = 0; }
    if (gid < 65536) {
        int c = gid >> 15;
        int b = (gid >> 14) & 1;
        int ji = gid & 16383;
        int j = ji >> 7, i2 = ji & 127;
        float v = W0[c * 16384 + i2 * 128 + j];   // H[c][b][j][i] = W0[c][i][j]
        float* H = (c == 0) ? g_H0A : g_H1A;
        H[b * 16384 + ji] = v;
    }
    if (blockIdx.x == 255) {
        __shared__ int any;
        if (threadIdx.x == 0) any = 0;
        __syncthreads();
        int lim = min(2048, E / 2);
        for (int i = threadIdx.x; i < lim; i += 256)
            if (ei32[2 * i + 1] != 0) any = 1;
        __syncthreads();
        if (threadIdx.x == 0) g_e64 = (any == 0) ? 1 : 0;
    }
    if (blockIdx.x == 254 && threadIdx.x < 64) {
        int w = threadIdx.x >> 5, l = threadIdx.x & 31;
        const float* pc = p + w * 128;
        float s = 0.f;
        for (int i = l; i < 128; i += 32) { float v = pc[i]; s += v * v; }
        #pragma unroll
        for (int o = 16; o > 0; o >>= 1) s += __shfl_down_sync(0xffffffffu, s, o);
        if (l == 0) g_pnorm[w] = sqrtf(s);
    }
}

// deg (blocks 0..1249) merged with scores0 (rest)
__global__ void deg_scores0_kernel(const void* ei, const float* __restrict__ ew, int E,
                                   const float* __restrict__ x, const float* __restrict__ p0) {
    if (blockIdx.x < 1250) {
        int e = blockIdx.x * 256 + threadIdx.x;
        if (e >= E) return;
        int s, t;
        read_edge(ei, e, E, s, t);
        atomicAdd(&g_deg[t], ew[e]);
        atomicAdd(&g_counts[t], 1);
        return;
    }
    int wid = ((blockIdx.x - 1250) << 3) + (threadIdx.x >> 5);
    if (wid >= NT * NB * NNODE) return;
    int lane = threadIdx.x & 31;
    int t = wid / (NB * NNODE);
    int rem = wid - t * (NB * NNODE);
    int b = rem / NNODE;
    int n = rem - b * NNODE;
    const float* xr = x + (((size_t)(b * NT + t)) * NNODE + n) * FDIM;
    float4 v = __ldg((const float4*)xr + lane);
    float4 pv = __ldg((const float4*)p0 + lane);
    float s = v.x * pv.x + v.y * pv.y + v.z * pv.z + v.w * pv.w;
    #pragma unroll
    for (int o = 16; o > 0; o >>= 1) s += __shfl_down_sync(0xffffffffu, s, o);
    if (lane == 0) g_scores0[wid] = s / g_pnorm[0];
}

__global__ void scan_kernel() {
    __shared__ int part[256];
    int tid = threadIdx.x;
    int start = tid * 40;
    int s = 0;
    for (int j = 0; j < 40; ++j) {
        int idx = start + j;
        if (idx < NNODE) s += g_counts[idx];
    }
    part[tid] = s;
    __syncthreads();
    for (int off = 1; off < 256; off <<= 1) {
        int v = (tid >= off) ? part[tid - off] : 0;
        __syncthreads();
        part[tid] += v;
        __syncthreads();
    }
    int run = part[tid] - s;
    for (int j = 0; j < 40; ++j) {
        int idx = start + j;
        if (idx < NNODE) {
            g_colptr[idx] = run; g_cursor[idx] = run;
            run += g_counts[idx];
            g_dinv[idx] = rsqrtf(g_deg[idx] + 1.0f);
        }
    }
    if (tid == 255) g_colptr[NNODE] = part[255];
}

// ================= roles =================

// ---- top-k 128 of 10000 + pool; templated block size; tb = t*2+b ----
#define TKCAP 1024
#define TOPK_SMEM 21760
template <int NTHR>
__device__ void topk_role(int tb, int mode, const float* __restrict__ x, char* smraw) {
    int* histW = (int*)smraw;                           // [8][256]
    unsigned int* cKey = (unsigned int*)(smraw + 8192);
    int* cIdx = (int*)(smraw + 12288);
    float* cVal = (float*)(smraw + 16384);
    int* rIdx = (int*)(smraw + 20480);
    float* rTanh = (float*)(smraw + 20992);
    int* scl = (int*)(smraw + 21504);

    int tid = threadIdx.x;
    int grp = tid / (NTHR / 8);   // 8 histogram groups

    const float* sc;
    const float* feat;
    float* pool;
    if (mode == 0) {
        int t = tb >> 1, b = tb & 1;
        sc = g_scores0 + (size_t)tb * NNODE;
        feat = x + ((size_t)(b * NT + t)) * BATCH;
        pool = g_pooled0 + (size_t)tb * 16384;
    } else {
        sc = g_scores1All + (size_t)tb * NNODE;
        feat = g_out0All + (size_t)tb * BATCH;
        pool = g_pooled1All + (size_t)tb * 16384;
    }

    unsigned int prefix = 0, pmask = 0;
    int K = 128;
    for (int shift = 24; shift >= 0; shift -= 8) {
        for (int i = tid; i < 8 * 256; i += NTHR) histW[i] = 0;
        __syncthreads();
        for (int n = tid; n < NNODE; n += NTHR) {
            unsigned int kk = fkey(sc[n]);
            if ((kk & pmask) == prefix) atomicAdd(&histW[grp * 256 + ((kk >> shift) & 255)], 1);
        }
        __syncthreads();
        if (tid < 256) {
            int s = 0;
            #pragma unroll
            for (int g = 0; g < 8; ++g) s += histW[g * 256 + tid];
            __syncthreads();
            histW[tid] = s;
        } else {
            __syncthreads();
        }
        __syncthreads();
        if (tid == 0) {
            int cum = 0, bsel = 0;
            for (int bkt = 255; bkt >= 0; --bkt) {
                int h = histW[bkt];
                if (cum + h >= K) { bsel = bkt; break; }
                cum += h;
            }
            scl[1] = bsel; scl[2] = cum;
        }
        __syncthreads();
        prefix |= ((unsigned int)scl[1]) << shift;
        pmask |= 0xFFu << shift;
        K -= scl[2];
        __syncthreads();
    }
    if (tid == 0) scl[0] = 0;
    __syncthreads();
    for (int n = tid; n < NNODE; n += NTHR) {
        float v = sc[n];
        unsigned int kk = fkey(v);
        if (kk >= prefix) {
            int pos = atomicAdd(&scl[0], 1);
            if (pos < TKCAP) { cKey[pos] = kk; cIdx[pos] = n; cVal[pos] = v; }
        }
    }
    __syncthreads();
    int C = min(scl[0], TKCAP);
    for (int i = tid; i < C; i += NTHR) {
        unsigned int ki = cKey[i];
        int ii = cIdx[i];
        int rank = 0;
        for (int j = 0; j < C; ++j) {
            unsigned int kj = cKey[j];
            rank += (kj > ki) || (kj == ki && cIdx[j] < ii);
        }
        if (rank < 128) { rIdx[rank] = ii; rTanh[rank] = tanhf(cVal[i]); }
    }
    __syncthreads();
    for (int i = tid; i < 4096; i += NTHR) {
        int row = i >> 5, q = i & 31;
        float4 v = __ldg((const float4*)(feat + (size_t)rIdx[row] * FDIM) + q);
        float s = rTanh[row];
        v.x *= s; v.y *= s; v.z *= s; v.w *= s;
        *((float4*)(pool + row * 128) + q) = v;
    }
}

// ---- GRU step; rb in [0,128) ----
__device__ void gru_role(int rb,
                         const float* __restrict__ xg, const float* __restrict__ Hin,
                         float* __restrict__ Hout, float* __restrict__ HTdst,
                         const float* __restrict__ w_ih, const float* __restrict__ w_hh,
                         const float* __restrict__ b_ih, const float* __restrict__ b_hh,
                         float* sm) {
    float* xs = sm;
    float* hs = sm + 528;
    float* wi = sm + 1056;
    float* wh = sm + 2640;
    int tid = threadIdx.x;
    int r0 = (rb & 15) * 16;
    int h0 = (rb >> 4) * 16;
    int hh = tid & 15, rr = tid >> 4;
    float acc[6] = {0.f, 0.f, 0.f, 0.f, 0.f, 0.f};

    for (int kc = 0; kc < 128; kc += 32) {
        for (int i = tid; i < 512; i += 256) {
            int r = i >> 5, k = i & 31;
            xs[r * 33 + k] = xg[(r0 + r) * 128 + kc + k];
            hs[r * 33 + k] = Hin[(r0 + r) * 128 + kc + k];
        }
        #pragma unroll
        for (int g = 0; g < 3; ++g)
            for (int i = tid; i < 512; i += 256) {
                int r = i >> 5, k = i & 31;
                wi[g * 528 + r * 33 + k] = w_ih[(g * 128 + h0 + r) * 128 + kc + k];
                wh[g * 528 + r * 33 + k] = w_hh[(g * 128 + h0 + r) * 128 + kc + k];
            }
        __syncthreads();
        #pragma unroll
        for (int k = 0; k < 32; ++k) {
            float xv = xs[rr * 33 + k], hv = hs[rr * 33 + k];
            acc[0] = fmaf(xv, wi[0 * 528 + hh * 33 + k], acc[0]);
            acc[1] = fmaf(xv, wi[1 * 528 + hh * 33 + k], acc[1]);
            acc[2] = fmaf(xv, wi[2 * 528 + hh * 33 + k], acc[2]);
            acc[3] = fmaf(hv, wh[0 * 528 + hh * 33 + k], acc[3]);
            acc[4] = fmaf(hv, wh[1 * 528 + hh * 33 + k], acc[4]);
            acc[5] = fmaf(hv, wh[2 * 528 + hh * 33 + k], acc[5]);
        }
        __syncthreads();
    }
    int row = r0 + rr, h = h0 + hh;
    float gir = acc[0] + b_ih[h], giz = acc[1] + b_ih[128 + h], gin = acc[2] + b_ih[256 + h];
    float ghr = acc[3] + b_hh[h], ghz = acc[4] + b_hh[128 + h], ghn = acc[5] + b_hh[256 + h];
    float r = 1.f / (1.f + expf(-(gir + ghr)));
    float z = 1.f / (1.f + expf(-(giz + ghz)));
    float n = tanhf(fmaf(r, ghn, gin));
    float hv = (1.f - z) * n + z * Hin[row * 128 + h];
    Hout[row * 128 + h] = hv;
    int b = row >> 7, j = row & 127;
    HTdst[(size_t)b * 16384 + h * 128 + j] = hv;
}

// ---- GEMM (split-K 32) + fused bias + relu + optional scores1 epilogue ----
__device__ void gemm_role(int rb, const float* __restrict__ A, long sy,
                          const float* __restrict__ HT, float* __restrict__ C,
                          const float* __restrict__ biasc,
                          float* __restrict__ scores, const float* __restrict__ p1,
                          float* sm) {
    float* As = sm;               // [64][32]
    float* Hs = sm + 64 * 32;     // [32][132]
    int idx = rb / 157;
    int rowBase = (rb % 157) * 64;
    const float* Ab = A + (size_t)idx * sy;
    const float* HTb = HT + (size_t)idx * 16384;
    float* Cb = C + (size_t)idx * BATCH;
    float* scb = scores ? (scores + (size_t)idx * NNODE) : (float*)0;
    int tid = threadIdx.x;
    int c0 = (tid & 15) * 4;
    int r0 = (tid >> 4) * 4;

    unsigned long long aA[4][2], aB[4][2];
    #pragma unroll
    for (int i = 0; i < 4; ++i) { aA[i][0] = aA[i][1] = aB[i][0] = aB[i][1] = 0ull; }

    #pragma unroll
    for (int kh = 0; kh < 4; ++kh) {
        if (kh) __syncthreads();
        for (int i = tid; i < 32 * 128; i += 256) {
            int k = i >> 7, j = i & 127;
            Hs[k * 132 + j] = HTb[(kh * 32 + k) * 128 + j];
        }
        for (int i = tid; i < 64 * 8; i += 256) {
            int r = i >> 3, c4 = i & 7;
            int row = rowBase + r;
            float4 v = (row < NNODE)
                ? __ldg((const float4*)(Ab + (size_t)row * 128 + kh * 32) + c4)
                : make_float4(0.f, 0.f, 0.f, 0.f);
            *((float4*)(As + r * 32) + c4) = v;
        }
        __syncthreads();
        const float* ar = As + r0 * 32;
        #pragma unroll 4
        for (int k = 0; k < 32; ++k) {
            ulonglong2 hA = *(const ulonglong2*)(Hs + k * 132 + c0);
            ulonglong2 hB = *(const ulonglong2*)(Hs + k * 132 + c0 + 64);
            #pragma unroll
            for (int i = 0; i < 4; ++i) {
                unsigned long long ap = pk2(ar[i * 32 + k]);
                FFMA2(aA[i][0], ap, hA.x);
                FFMA2(aA[i][1], ap, hA.y);
                FFMA2(aB[i][0], ap, hB.x);
                FFMA2(aB[i][1], ap, hB.y);
            }
        }
    }
    float4 bb0 = __ldg((const float4*)(biasc + c0));
    float4 bb1 = __ldg((const float4*)(biasc + c0 + 64));
    float4 pv0 = make_float4(0.f, 0.f, 0.f, 0.f), pv1 = pv0;
    if (scb) {
        pv0 = __ldg((const float4*)(p1 + c0));
        pv1 = __ldg((const float4*)(p1 + c0 + 64));
    }
    float pinv = scb ? (1.f / g_pnorm[1]) : 0.f;
    #pragma unroll
    for (int i = 0; i < 4; ++i) {
        int row = rowBase + r0 + i;
        float2 l0 = up2(aA[i][0]), l1 = up2(aA[i][1]);
        float2 m0 = up2(aB[i][0]), m1 = up2(aB[i][1]);
        float o0 = fmaxf(l0.x + bb0.x, 0.f), o1 = fmaxf(l0.y + bb0.y, 0.f);
        float o2 = fmaxf(l1.x + bb0.z, 0.f), o3 = fmaxf(l1.y + bb0.w, 0.f);
        float o4 = fmaxf(m0.x + bb1.x, 0.f), o5 = fmaxf(m0.y + bb1.y, 0.f);
        float o6 = fmaxf(m1.x + bb1.z, 0.f), o7 = fmaxf(m1.y + bb1.w, 0.f);
        if (row < NNODE) {
            *((float4*)(Cb + (size_t)row * 128 + c0)) = make_float4(o0, o1, o2, o3);
            *((float4*)(Cb + (size_t)row * 128 + c0 + 64)) = make_float4(o4, o5, o6, o7);
        }
        if (scb) {
            float s = o0 * pv0.x + o1 * pv0.y + o2 * pv0.z + o3 * pv0.w
                    + o4 * pv1.x + o5 * pv1.y + o6 * pv1.z + o7 * pv1.w;
            #pragma unroll
            for (int off = 8; off > 0; off >>= 1)
                s += __shfl_down_sync(0xffffffffu, s, off, 16);
            if ((tid & 15) == 0 && row < NNODE) scb[row] = s * pinv;
        }
    }
}

// ---- RAW propagation (P * src): 4 nodes per block ----
__device__ void prop_role(int rb, const float* __restrict__ src, long srcStride,
                          float* __restrict__ dst, long dstStride) {
    int tid = threadIdx.x;
    int sub = tid >> 6;
    int b = (tid >> 5) & 1;
    int q = tid & 31;
    int i = rb * 4 + sub;
    const float* tb = src + (size_t)b * srcStride;
    int e0 = g_colptr[i], e1 = g_colptr[i + 1];
    float4 acc = make_float4(0.f, 0.f, 0.f, 0.f);

    int e = e0;
    for (; e + 4 <= e1; e += 4) {
        int2 c0v = __ldg(&g_csr[e]);
        int2 c1v = __ldg(&g_csr[e + 1]);
        int2 c2v = __ldg(&g_csr[e + 2]);
        int2 c3v = __ldg(&g_csr[e + 3]);
        float4 r0 = __ldg((const float4*)(tb + (size_t)c0v.x * 128) + q);
        float4 r1 = __ldg((const float4*)(tb + (size_t)c1v.x * 128) + q);
        float4 r2 = __ldg((const float4*)(tb + (size_t)c2v.x * 128) + q);
        float4 r3 = __ldg((const float4*)(tb + (size_t)c3v.x * 128) + q);
        float v0 = __int_as_float(c0v.y), v1 = __int_as_float(c1v.y);
        float v2 = __int_as_float(c2v.y), v3 = __int_as_float(c3v.y);
        acc.x = fmaf(v0, r0.x, acc.x); acc.y = fmaf(v0, r0.y, acc.y);
        acc.z = fmaf(v0, r0.z, acc.z); acc.w = fmaf(v0, r0.w, acc.w);
        acc.x = fmaf(v1, r1.x, acc.x); acc.y = fmaf(v1, r1.y, acc.y);
        acc.z = fmaf(v1, r1.z, acc.z); acc.w = fmaf(v1, r1.w, acc.w);
        acc.x = fmaf(v2, r2.x, acc.x); acc.y = fmaf(v2, r2.y, acc.y);
        acc.z = fmaf(v2, r2.z, acc.z); acc.w = fmaf(v2, r2.w, acc.w);
        acc.x = fmaf(v3, r3.x, acc.x); acc.y = fmaf(v3, r3.y, acc.y);
        acc.z = fmaf(v3, r3.z, acc.z); acc.w = fmaf(v3, r3.w, acc.w);
    }
    for (; e < e1; ++e) {
        int2 sv = __ldg(&g_csr[e]);
        float v = __int_as_float(sv.y);
        float4 r = __ldg((const float4*)(tb + (size_t)sv.x * 128) + q);
        acc.x = fmaf(v, r.x, acc.x); acc.y = fmaf(v, r.y, acc.y);
        acc.z = fmaf(v, r.z, acc.z); acc.w = fmaf(v, r.w, acc.w);
    }
    float di = g_dinv[i];
    size_t soff = (size_t)i * 128;
    float4 sv = __ldg((const float4*)(tb + soff) + q);
    acc.x = fmaf(di, sv.x, acc.x); acc.y = fmaf(di, sv.y, acc.y);
    acc.z = fmaf(di, sv.z, acc.z); acc.w = fmaf(di, sv.w, acc.w);
    float4 o;
    o.x = di * acc.x; o.y = di * acc.y; o.z = di * acc.z; o.w = di * acc.w;
    *((float4*)(dst + (size_t)b * dstStride + soff) + q) = o;
}

// ================= mega kernel (256 threads, small roles first) =================
#define PIPE_SMEM 25088
__global__ void __launch_bounds__(256) pipe_kernel(
        int nGemm, const float* gA, long gSy, const float* gHT, float* gC,
        const float* gBias, float* gScores, const float* gP1,
        int nTopk, int topkTbBase, const float* x,
        int nGruA, const float* aXg, const float* aHin, float* aHout, float* aHT,
        const float* aWih, const float* aWhh, const float* aBih, const float* aBhh,
        int nGruB, const float* bXg, const float* bHin, float* bHout, float* bHT,
        const float* bWih, const float* bWhh, const float* bBih, const float* bBhh,
        int nProp, const float* pSrc, long pSrcStride, float* pDst, long pDstStride) {
    extern __shared__ char sm[];
    int rb = blockIdx.x;
    if (rb < nGemm) { gemm_role(rb, gA, gSy, gHT, gC, gBias, gScores, gP1, (float*)sm); return; }
    rb -= nGemm;
    if (rb < nTopk) { topk_role<256>(topkTbBase + rb, 1, x, sm); return; }
    rb -= nTopk;
    if (rb < nGruA) { gru_role(rb, aXg, aHin, aHout, aHT, aWih, aWhh, aBih, aBhh, (float*)sm); return; }
    rb -= nGruA;
    if (rb < nGruB) { gru_role(rb, bXg, bHin, bHout, bHT, bWih, bWhh, bBih, bBhh, (float*)sm); return; }
    rb -= nGruB;
    if (rb < nProp) { prop_role(rb, pSrc, pSrcStride, pDst, pDstStride); }
}

// fill (CSR) merged with layer-0 topk — 1024 threads (topk is the pre-phase long pole)
__global__ void __launch_bounds__(1024) fill_topk0_kernel(const void* ei,
                                                          const float* __restrict__ ew, int E,
                                                          const float* __restrict__ x) {
    extern __shared__ char sm[];
    if (blockIdx.x < 16) { topk_role<1024>(blockIdx.x, 0, x, sm); return; }
    int e = (blockIdx.x - 16) * 1024 + threadIdx.x;
    if (e >= E) return;
    int s, t;
    read_edge(ei, e, E, s, t);
    int pos = atomicAdd(&g_cursor[t], 1);
    g_csr[pos] = make_int2(s, __float_as_int(g_dinv[s] * ew[e]));
}

// ---------------- launcher ----------------
extern "C" void kernel_launch(void* const* d_in, const int* in_sizes, int n_in,
                              void* d_out, int out_size) {
    const float* x   = (const float*)d_in[0];
    const void*  ei  = d_in[1];
    const float* ew  = (const float*)d_in[2];
    const float* W0  = (const float*)d_in[3];
    const float* p   = (const float*)d_in[4];
    const float* wih = (const float*)d_in[5];
    const float* whh = (const float*)d_in[6];
    const float* bih = (const float*)d_in[7];
    const float* bhh = (const float*)d_in[8];
    const float* bias = (const float*)d_in[9];
    float* dout = (float*)d_out;
    int E = in_sizes[2];

    cudaFuncSetAttribute(pipe_kernel, cudaFuncAttributeMaxDynamicSharedMemorySize, PIPE_SMEM);
    cudaFuncSetAttribute(fill_topk0_kernel, cudaFuncAttributeMaxDynamicSharedMemorySize, TOPK_SMEM);

    float *pH0A, *pH0B, *pH1A, *pH1B, *pHT0, *pHT1, *pP0, *pP1, *pPx, *pOut0, *pSc1;
    cudaGetSymbolAddress((void**)&pH0A, g_H0A);
    cudaGetSymbolAddress((void**)&pH0B, g_H0B);
    cudaGetSymbolAddress((void**)&pH1A, g_H1A);
    cudaGetSymbolAddress((void**)&pH1B, g_H1B);
    cudaGetSymbolAddress((void**)&pHT0, g_HT0All);
    cudaGetSymbolAddress((void**)&pHT1, g_HT1);
    cudaGetSymbolAddress((void**)&pP0, g_pooled0);
    cudaGetSymbolAddress((void**)&pP1, g_pooled1All);
    cudaGetSymbolAddress((void**)&pPx, g_PxAll);
    cudaGetSymbolAddress((void**)&pOut0, g_out0All);
    cudaGetSymbolAddress((void**)&pSc1, g_scores1All);

    const float* p1 = p + 128;
    const float* wih1 = wih + 49152;
    const float* whh1 = whh + 49152;
    const float* bih1 = bih + 384;
    const float* bhh1 = bhh + 384;

    // ---- pre-phase ----
    init_kernel<<<256, 256>>>((const int*)ei, E, p, W0);
    deg_scores0_kernel<<<1250 + 20000, 256>>>(ei, ew, E, x, p);
    scan_kernel<<<1, 256>>>();
    fill_topk0_kernel<<<16 + (E + 1023) / 1024, 1024, TOPK_SMEM>>>(ei, ew, E, x);

    // ---- pipeline: L(t) = gemm(t-1) | topk1(t-2) | gru0(t) | gru1(t-3) | prop_x(t) ----
    for (int t = 0; t < 8; ++t) {
        int gt = (t >= 1) ? (t - 1) : 0;
        int kt = (t >= 2) ? (t - 2) : 0;
        int sB = (t >= 3) ? (t - 3) : 0;
        int nGemm = (t >= 1) ? 314 : 0;
        int nTopk = (t >= 2) ? 2 : 0;
        int nGruB = (t >= 3) ? 128 : 0;
        int total = nGemm + nTopk + 128 + nGruB + 2500;
        pipe_kernel<<<total, 256, PIPE_SMEM>>>(
            nGemm, pPx + (size_t)gt * 2 * BATCH, (long)BATCH,
            pHT0 + (size_t)gt * NB * 16384, pOut0 + (size_t)gt * 2 * BATCH,
            bias, pSc1 + (size_t)gt * 2 * NNODE, p1,
            nTopk, kt * 2, x,
            128, pP0 + (size_t)t * 32768,
            (t & 1) ? pH0B : pH0A, (t & 1) ? pH0A : pH0B,
            pHT0 + (size_t)t * NB * 16384, wih, whh, bih, bhh,
            nGruB, pP1 + (size_t)sB * 32768,
            (sB & 1) ? pH1B : pH1A, (sB & 1) ? pH1A : pH1B,
            pHT1, wih1, whh1, bih1, bhh1,
            2500, x + (size_t)t * BATCH, (long)NT * BATCH,
            pPx + (size_t)t * 2 * BATCH, (long)BATCH);
    }
    // L8: gemm(7) + topk1(6) + gru1(5)
    pipe_kernel<<<314 + 2 + 128, 256, PIPE_SMEM>>>(
        314, pPx + (size_t)14 * BATCH, (long)BATCH,
        pHT0 + (size_t)7 * NB * 16384, pOut0 + (size_t)14 * BATCH,
        bias, pSc1 + (size_t)14 * NNODE, p1,
        2, 12, x,
        0, pP0, pH0A, pH0B, pHT0, wih, whh, bih, bhh,
        128, pP1 + (size_t)5 * 32768, pH1B, pH1A, pHT1, wih1, whh1, bih1, bhh1,
        0, x, 0L, pPx, 0L);
    // L9: topk1(7) + gru1(6) + prop_final (P * out0_7 -> pPx[0..2B))
    pipe_kernel<<<2 + 128 + 2500, 256, PIPE_SMEM>>>(
        0, pPx, (long)BATCH, pHT0, pOut0, bias, (float*)0, p1,
        2, 14, x,
        0, pP0, pH0A, pH0B, pHT0, wih, whh, bih, bhh,
        128, pP1 + (size_t)6 * 32768, pH1A, pH1B, pHT1, wih1, whh1, bih1, bhh1,
        2500, pOut0 + (size_t)14 * BATCH, (long)BATCH, pPx, (long)BATCH);
    // L10: gru1(7)
    pipe_kernel<<<128, 256, PIPE_SMEM>>>(
        0, pPx, (long)BATCH, pHT0, pOut0, bias, (float*)0, p1,
        0, 0, x,
        0, pP0, pH0A, pH0B, pHT0, wih, whh, bih, bhh,
        128, pP1 + (size_t)7 * 32768, pH1B, pH1A, pHT1, wih1, whh1, bih1, bhh1,
        0, x, 0L, pPx, 0L);
    // L11: gemm_final: relu((P out0_7) @ W1_7 + bias1) -> dout
    pipe_kernel<<<314, 256, PIPE_SMEM>>>(
        314, pPx, (long)BATCH, pHT1, dout, bias + 128, (float*)0, p1,
        0, 0, x,
        0, pP0, pH0A, pH0B, pHT0, wih, whh, bih, bhh,
        0, pP1, pH1A, pH1B, pHT1, wih1, whh1, bih1, bhh1,
        0, x, 0L, pPx, 0L);
}